// round 6
// baseline (speedup 1.0000x reference)
#include <cuda_runtime.h>
#include <math.h>
#include <float.h>

// ---------------- problem constants ----------------
namespace {
constexpr int S_ = 2048, D_ = 2048, H_ = 16, DN_ = 128, DR_ = 64, DV_ = 128;
constexpr int R_ = 512, HI_ = 4, DI_ = 64, KTOP_ = 512, E_ = 4, DFF_ = 8192;
constexpr int QD  = H_ * (DN_ + DR_);   // 3072
constexpr int KVD = H_ * (DN_ + DV_);   // 4096
}

// ---------------- scratch (device globals; no allocation) ----------------
__device__ float g_h   [(size_t)S_*D_];
__device__ float g_q   [(size_t)S_*QD];
__device__ float g_ckv [(size_t)S_*(R_+DR_)];
__device__ float g_c   [(size_t)S_*R_];
__device__ float g_kv  [(size_t)S_*KVD];
__device__ float g_kr  [(size_t)S_*DR_];
__device__ float g_qi  [(size_t)S_*HI_*DI_];
__device__ float g_ki  [(size_t)S_*DI_];
__device__ float g_wgt [(size_t)S_*HI_];
__device__ float g_o   [(size_t)S_*H_*DV_];
__device__ float g_x1  [(size_t)S_*D_];
__device__ float g_h2  [(size_t)S_*D_];
__device__ float g_rlog[(size_t)S_*E_];
__device__ float g_hid [(size_t)E_*S_*DFF_];   // 268 MB MoE activations
__device__ int   g_sel   [(size_t)S_*KTOP_];
__device__ int   g_selcnt[S_];
__device__ int   g_ecnt  [E_];
__device__ int   g_elist [E_*S_];
__device__ float g_egate [E_*S_];
__device__ float g_epsum [E_];

// ---------------- rmsnorm ----------------
__global__ void rms_kernel(const float* __restrict__ x, int istride,
                           const float* __restrict__ w, float* __restrict__ out, int n) {
    int row = blockIdx.x;
    const float* xr = x + (size_t)row * istride;
    __shared__ float red[256];
    float s = 0.f;
    for (int d = threadIdx.x; d < n; d += 256) { float v = xr[d]; s += v * v; }
    red[threadIdx.x] = s;
    __syncthreads();
    for (int o = 128; o > 0; o >>= 1) {
        if (threadIdx.x < o) red[threadIdx.x] += red[threadIdx.x + o];
        __syncthreads();
    }
    float scale = rsqrtf(red[0] / (float)n + 1e-6f);
    for (int d = threadIdx.x; d < n; d += 256)
        out[(size_t)row * n + d] = xr[d] * scale * w[d];
}

// ---------------- generic SGEMM 128x128x8, 256 threads, 8x8/thread ----------------
// MODE 0: C = A@B
// MODE 1: MoE up:  rows gathered via rowmap[e*S+m], C[e*S+m] = gelu(acc + bias_e[n])
// MODE 2: MoE down: A = hid compact rows (e*S+m), scatter atomicAdd C[tok] += gate*(acc + bias_e[n])
// MODE 3: C = A@B + extra (residual)
__device__ __forceinline__ float gelu_exact(float t) {
    return 0.5f * t * (1.0f + erff(t * 0.7071067811865475f));
}

template<int MODE>
__global__ void sgemm_kernel(const float* __restrict__ A, const float* __restrict__ Bm,
                             float* __restrict__ C, int M, int N, int K,
                             const float* __restrict__ extra,
                             const int* __restrict__ rowmap,
                             const float* __restrict__ gates,
                             const int* __restrict__ cnt) {
    constexpr int BM = 128, BN = 128, BK = 8;
    __shared__ float As[BK][BM];
    __shared__ float Bs[BK][BN];
    int e = blockIdx.z;
    int Me = M;
    const float* Bp = Bm;
    const float* bias = extra;
    if (MODE == 1 || MODE == 2) {
        Me = cnt[e];
        Bp = Bm + (size_t)e * K * N;
        bias = extra + (size_t)e * N;
    }
    int row0 = blockIdx.y * BM;
    int col0 = blockIdx.x * BN;
    if (row0 >= Me) return;
    int tid = threadIdx.x;
    int rm = (tid / 16) * 8;
    int rn = (tid % 16) * 8;
    float acc[8][8];
#pragma unroll
    for (int i = 0; i < 8; i++)
#pragma unroll
        for (int j = 0; j < 8; j++) acc[i][j] = 0.f;

    for (int k0 = 0; k0 < K; k0 += BK) {
#pragma unroll
        for (int i = 0; i < 4; i++) {
            int lin = tid + i * 256;
            int m = lin >> 3, kk = lin & 7;
            int gm = row0 + m;
            float v = 0.f;
            if (gm < Me) {
                int ar;
                if (MODE == 1)      ar = rowmap[e * S_ + gm];
                else if (MODE == 2) ar = e * S_ + gm;
                else                ar = gm;
                v = A[(size_t)ar * K + k0 + kk];
            }
            As[kk][m] = v;
        }
#pragma unroll
        for (int i = 0; i < 4; i++) {
            int lin = tid + i * 256;
            int n = lin & 127, kk = lin >> 7;
            int gn = col0 + n;
            float v = 0.f;
            if (gn < N) v = Bp[(size_t)(k0 + kk) * N + gn];
            Bs[kk][n] = v;
        }
        __syncthreads();
#pragma unroll
        for (int kk = 0; kk < BK; kk++) {
            float a[8], b[8];
#pragma unroll
            for (int i = 0; i < 8; i++) a[i] = As[kk][rm + i];
#pragma unroll
            for (int j = 0; j < 8; j++) b[j] = Bs[kk][rn + j];
#pragma unroll
            for (int i = 0; i < 8; i++)
#pragma unroll
                for (int j = 0; j < 8; j++) acc[i][j] += a[i] * b[j];
        }
        __syncthreads();
    }
#pragma unroll
    for (int i = 0; i < 8; i++) {
        int gm = row0 + rm + i;
        if (gm >= Me) continue;
#pragma unroll
        for (int j = 0; j < 8; j++) {
            int gn = col0 + rn + j;
            if (gn >= N) continue;
            float v = acc[i][j];
            if (MODE == 0) {
                C[(size_t)gm * N + gn] = v;
            } else if (MODE == 3) {
                C[(size_t)gm * N + gn] = v + extra[(size_t)gm * N + gn];
            } else if (MODE == 1) {
                C[(size_t)(e * S_ + gm) * N + gn] = gelu_exact(v + bias[gn]);
            } else { // MODE 2
                int tr = rowmap[e * S_ + gm];
                atomicAdd(&C[(size_t)tr * N + gn], gates[e * S_ + gm] * (v + bias[gn]));
            }
        }
    }
}

// ---------------- RoPE (q in-place, k_rope -> g_kr) ----------------
__global__ void rope_kernel() {
    int s = blockIdx.x;
    int tid = threadIdx.x;
    for (int t = tid; t < H_ * 32; t += blockDim.x) {
        int h = t >> 5, i = t & 31;
        float freq = powf(10000.f, -(float)i / 32.f);
        float ang = (float)s * freq;
        float cs = cosf(ang), sn = sinf(ang);
        float* p = g_q + (size_t)s * QD + h * (DN_ + DR_) + DN_;
        float a = p[i], b = p[i + 32];
        p[i]      = a * cs - b * sn;
        p[i + 32] = b * cs + a * sn;
    }
    if (tid < 32) {
        int i = tid;
        float freq = powf(10000.f, -(float)i / 32.f);
        float ang = (float)s * freq;
        float cs = cosf(ang), sn = sinf(ang);
        const float* p = g_ckv + (size_t)s * (R_ + DR_) + R_;
        float a = p[i], b = p[i + 32];
        g_kr[(size_t)s * DR_ + i]      = a * cs - b * sn;
        g_kr[(size_t)s * DR_ + i + 32] = b * cs + a * sn;
    }
}

// ---------------- indexer scores (writes masked idx_scores output) ----------------
__global__ void idx_kernel(float* __restrict__ idx_out) {
    int q = blockIdx.x;
    __shared__ float qs[HI_ * DI_];
    __shared__ float wq[HI_];
    __shared__ float kis[128 * 65];
    int tid = threadIdx.x; // 128
    for (int t = tid; t < HI_ * DI_; t += 128) qs[t] = g_qi[(size_t)q * HI_ * DI_ + t];
    if (tid < HI_) wq[tid] = g_wgt[q * HI_ + tid];
    for (int kt = 0; kt < S_; kt += 128) {
        __syncthreads();
        for (int t = tid; t < 128 * DI_; t += 128)
            kis[(t >> 6) * 65 + (t & 63)] = g_ki[(size_t)kt * DI_ + t];
        __syncthreads();
        int k = kt + tid;
        float sc;
        if (k > q) {
            sc = -FLT_MAX;
        } else {
            sc = 0.f;
            const float* krw = &kis[tid * 65];
#pragma unroll
            for (int h = 0; h < HI_; h++) {
                float d = 0.f;
#pragma unroll 8
                for (int dd = 0; dd < DI_; dd++) d += qs[h * DI_ + dd] * krw[dd];
                sc += wq[h] * fmaxf(d, 0.f);
            }
        }
        idx_out[(size_t)q * S_ + k] = sc;
    }
}

// ---------------- exact top-k (radix select, jax tie-break: smallest index) ----------------
__device__ __forceinline__ unsigned fkey(float f) {
    unsigned u = __float_as_uint(f);
    return (u & 0x80000000u) ? ~u : (u | 0x80000000u);
}

__global__ void topk_kernel(const float* __restrict__ idx_scores) {
    int q = blockIdx.x;
    int n = q + 1;
    int tid = threadIdx.x; // 256
    if (n <= KTOP_) {
        for (int k = tid; k < n; k += blockDim.x) g_sel[(size_t)q * KTOP_ + k] = k;
        if (tid == 0) g_selcnt[q] = n;
        return;
    }
    const float* row = idx_scores + (size_t)q * S_;
    __shared__ unsigned hist[256];
    __shared__ unsigned sh_prefix;
    __shared__ int sh_rem;
    __shared__ int sh_cnt;
    if (tid == 0) { sh_prefix = 0u; sh_rem = KTOP_; sh_cnt = 0; }
    __syncthreads();
    for (int p = 3; p >= 0; p--) {
        for (int b = tid; b < 256; b += blockDim.x) hist[b] = 0u;
        __syncthreads();
        unsigned pre = sh_prefix;
        int shift = 8 * (p + 1);
        for (int k = tid; k < n; k += blockDim.x) {
            unsigned u = fkey(row[k]);
            bool ok = (p == 3) || ((u >> shift) == (pre >> shift));
            if (ok) atomicAdd(&hist[(u >> (8 * p)) & 255u], 1u);
        }
        __syncthreads();
        if (tid == 0) {
            int rem = sh_rem;
            int d;
            for (d = 255; d >= 0; d--) {
                int c = (int)hist[d];
                if (c >= rem) break;
                rem -= c;
            }
            if (d < 0) d = 0;
            sh_prefix = pre | ((unsigned)d << (8 * p));
            sh_rem = rem;
        }
        __syncthreads();
    }
    unsigned T = sh_prefix;
    for (int k = tid; k < n; k += blockDim.x) {
        unsigned u = fkey(row[k]);
        if (u > T) {
            int pos = atomicAdd(&sh_cnt, 1);
            g_sel[(size_t)q * KTOP_ + pos] = k;
        }
    }
    __syncthreads();
    if (tid == 0) {
        int need = sh_rem;         // how many ties at T to include
        int base = sh_cnt;
        int taken = 0;
        for (int k = 0; k < n && taken < need; k++) {
            if (fkey(row[k]) == T) { g_sel[(size_t)q * KTOP_ + base + taken] = k; taken++; }
        }
        g_selcnt[q] = base + taken;   // == 512
    }
}

// ---------------- sparse attention over selected keys ----------------
__global__ void attn_kernel() {
    int s = blockIdx.x, h = blockIdx.y;
    int tid = threadIdx.x; // 128
    __shared__ float qf[DN_ + DR_];
    __shared__ float sc[KTOP_];
    __shared__ float red[128];
    // NOTE: DN_+DR_ = 192 > blockDim (128) -> must stride the load
    for (int d = tid; d < DN_ + DR_; d += 128)
        qf[d] = g_q[(size_t)s * QD + h * (DN_ + DR_) + d];
    int cnt = g_selcnt[s];
    __syncthreads();
    int warp = tid >> 5, lane = tid & 31;
    const float scale = 0.07216878364870323f; // 1/sqrt(192)
    for (int j = warp; j < cnt; j += 4) {
        int k = g_sel[(size_t)s * KTOP_ + j];
        const float* kn = g_kv + (size_t)k * KVD + h * (DN_ + DV_);
        float p = 0.f;
        for (int d = lane; d < DN_; d += 32) p += qf[d] * kn[d];
        const float* kp = g_kr + (size_t)k * DR_;
        for (int d = lane; d < DR_; d += 32) p += qf[DN_ + d] * kp[d];
#pragma unroll
        for (int o = 16; o > 0; o >>= 1) p += __shfl_down_sync(0xffffffffu, p, o);
        if (lane == 0) sc[j] = p * scale;
    }
    __syncthreads();
    float m = -FLT_MAX;
    for (int j = tid; j < cnt; j += 128) m = fmaxf(m, sc[j]);
    red[tid] = m; __syncthreads();
    for (int o = 64; o > 0; o >>= 1) { if (tid < o) red[tid] = fmaxf(red[tid], red[tid + o]); __syncthreads(); }
    m = red[0];
    __syncthreads();
    float ssum = 0.f;
    for (int j = tid; j < cnt; j += 128) { float e = expf(sc[j] - m); sc[j] = e; ssum += e; }
    red[tid] = ssum; __syncthreads();
    for (int o = 64; o > 0; o >>= 1) { if (tid < o) red[tid] += red[tid + o]; __syncthreads(); }
    float inv = 1.f / red[0];
    __syncthreads();
    float acc = 0.f;
    for (int j = 0; j < cnt; j++) {
        int k = g_sel[(size_t)s * KTOP_ + j];
        acc += sc[j] * g_kv[(size_t)k * KVD + h * (DN_ + DV_) + DN_ + tid];
    }
    g_o[(size_t)s * (H_ * DV_) + h * DV_ + tid] = acc * inv;
}

// ---------------- router / MoE bookkeeping ----------------
__global__ void zero_small_kernel() {
    int t = threadIdx.x;
    if (t < E_) { g_ecnt[t] = 0; g_epsum[t] = 0.f; }
}

__global__ void router_kernel() {
    int t = blockIdx.x * blockDim.x + threadIdx.x;
    if (t >= S_) return;
    float l[E_];
    float m = -FLT_MAX;
#pragma unroll
    for (int e = 0; e < E_; e++) { l[e] = g_rlog[t * E_ + e]; m = fmaxf(m, l[e]); }
    float sum = 0.f;
#pragma unroll
    for (int e = 0; e < E_; e++) { l[e] = expf(l[e] - m); sum += l[e]; }
    float inv = 1.f / sum;
    float p[E_];
#pragma unroll
    for (int e = 0; e < E_; e++) { p[e] = l[e] * inv; atomicAdd(&g_epsum[e], p[e]); }
    int i0 = 0;
#pragma unroll
    for (int e = 1; e < E_; e++) if (p[e] > p[i0]) i0 = e;
    int i1 = -1;
#pragma unroll
    for (int e = 0; e < E_; e++) if (e != i0 && (i1 < 0 || p[e] > p[i1])) i1 = e;
    float g0 = p[i0], g1 = p[i1];
    float dn = g0 + g1;
    g0 /= dn; g1 /= dn;
    int s0 = atomicAdd(&g_ecnt[i0], 1);
    g_elist[i0 * S_ + s0] = t; g_egate[i0 * S_ + s0] = g0;
    int s1 = atomicAdd(&g_ecnt[i1], 1);
    g_elist[i1 * S_ + s1] = t; g_egate[i1 * S_ + s1] = g1;
}

__global__ void copy_kernel(float* __restrict__ dst, const float* __restrict__ src, int n) {
    int i = blockIdx.x * blockDim.x + threadIdx.x;
    if (i < n) dst[i] = src[i];
}

__global__ void aux_kernel(float* out) {
    float a = 0.f;
    for (int e = 0; e < E_; e++)
        a += ((float)g_ecnt[e] / (float)S_) * (g_epsum[e] / (float)S_);
    *out = (float)E_ * a;
}

// ---------------- launch ----------------
static inline dim3 gemm_grid(int M, int N, int Z = 1) {
    return dim3((N + 127) / 128, (M + 127) / 128, Z);
}

extern "C" void kernel_launch(void* const* d_in, const int* in_sizes, int n_in,
                              void* d_out, int out_size) {
    const float* x        = (const float*)d_in[0];
    const float* norm1_w  = (const float*)d_in[1];
    const float* norm2_w  = (const float*)d_in[2];
    const float* kv_norm_w= (const float*)d_in[3];
    const float* Wq       = (const float*)d_in[4];
    const float* Wkva     = (const float*)d_in[5];
    const float* Wkvb     = (const float*)d_in[6];
    const float* Wo       = (const float*)d_in[7];
    const float* Wiq      = (const float*)d_in[8];
    const float* Wik      = (const float*)d_in[9];
    const float* Wiw      = (const float*)d_in[10];
    const float* Wr       = (const float*)d_in[11];
    const float* W1       = (const float*)d_in[12];
    const float* b1       = (const float*)d_in[13];
    const float* W2       = (const float*)d_in[14];
    const float* b2       = (const float*)d_in[15];

    float* out     = (float*)d_out;
    float* out_x   = out;
    float* out_aux = out + (size_t)S_ * D_;
    float* out_idx = out + (size_t)S_ * D_ + 1;

    void *ph, *pq, *pckv, *pc, *pkv, *pqi, *pki, *pwgt, *po, *px1, *ph2, *prlog, *phid,
         *pelist, *pegate, *pecnt;
    cudaGetSymbolAddress(&ph, g_h);
    cudaGetSymbolAddress(&pq, g_q);
    cudaGetSymbolAddress(&pckv, g_ckv);
    cudaGetSymbolAddress(&pc, g_c);
    cudaGetSymbolAddress(&pkv, g_kv);
    cudaGetSymbolAddress(&pqi, g_qi);
    cudaGetSymbolAddress(&pki, g_ki);
    cudaGetSymbolAddress(&pwgt, g_wgt);
    cudaGetSymbolAddress(&po, g_o);
    cudaGetSymbolAddress(&px1, g_x1);
    cudaGetSymbolAddress(&ph2, g_h2);
    cudaGetSymbolAddress(&prlog, g_rlog);
    cudaGetSymbolAddress(&phid, g_hid);
    cudaGetSymbolAddress(&pelist, g_elist);
    cudaGetSymbolAddress(&pegate, g_egate);
    cudaGetSymbolAddress(&pecnt, g_ecnt);

    float* H   = (float*)ph;
    float* Q   = (float*)pq;
    float* CKV = (float*)pckv;
    float* Cn  = (float*)pc;
    float* KV  = (float*)pkv;
    float* QI  = (float*)pqi;
    float* KI  = (float*)pki;
    float* WGT = (float*)pwgt;
    float* O   = (float*)po;
    float* X1  = (float*)px1;
    float* H2  = (float*)ph2;
    float* RL  = (float*)prlog;
    float* HID = (float*)phid;
    int*   EL  = (int*)pelist;
    float* EG  = (float*)pegate;
    int*   EC  = (int*)pecnt;

    // 1. h = rms(x, norm1_w)
    rms_kernel<<<S_, 256>>>(x, D_, norm1_w, H, D_);
    // 2. q = h@Wq
    sgemm_kernel<0><<<gemm_grid(S_, QD), 256>>>(H, Wq, Q, S_, QD, D_, nullptr, nullptr, nullptr, nullptr);
    // 3. ckv = h@Wkva
    sgemm_kernel<0><<<gemm_grid(S_, R_ + DR_), 256>>>(H, Wkva, CKV, S_, R_ + DR_, D_, nullptr, nullptr, nullptr, nullptr);
    // 4. indexer projections
    sgemm_kernel<0><<<gemm_grid(S_, HI_ * DI_), 256>>>(H, Wiq, QI, S_, HI_ * DI_, D_, nullptr, nullptr, nullptr, nullptr);
    sgemm_kernel<0><<<gemm_grid(S_, DI_), 256>>>(H, Wik, KI, S_, DI_, D_, nullptr, nullptr, nullptr, nullptr);
    sgemm_kernel<0><<<gemm_grid(S_, HI_), 256>>>(H, Wiw, WGT, S_, HI_, D_, nullptr, nullptr, nullptr, nullptr);
    // 5. c = rms(ckv[:, :R], kv_norm_w)
    rms_kernel<<<S_, 256>>>(CKV, R_ + DR_, kv_norm_w, Cn, R_);
    // 6. kv = c@Wkvb
    sgemm_kernel<0><<<gemm_grid(S_, KVD), 256>>>(Cn, Wkvb, KV, S_, KVD, R_, nullptr, nullptr, nullptr, nullptr);
    // 7. RoPE
    rope_kernel<<<S_, 256>>>();
    // 8. indexer scores (also output idx_scores)
    idx_kernel<<<S_, 128>>>(out_idx);
    // 9. top-k selection
    topk_kernel<<<S_, 256>>>(out_idx);
    // 10. sparse attention
    attn_kernel<<<dim3(S_, H_), 128>>>();
    // 11. x1 = o@Wo + x
    sgemm_kernel<3><<<gemm_grid(S_, D_), 256>>>(O, Wo, X1, S_, D_, H_ * DV_, x, nullptr, nullptr, nullptr);
    // 12. h2 = rms(x1, norm2_w)
    rms_kernel<<<S_, 256>>>(X1, D_, norm2_w, H2, D_);
    // 13. router logits
    sgemm_kernel<0><<<gemm_grid(S_, E_), 256>>>(H2, Wr, RL, S_, E_, D_, nullptr, nullptr, nullptr, nullptr);
    // 14. router: top-2, gates, per-expert lists
    zero_small_kernel<<<1, 32>>>();
    router_kernel<<<S_ / 256, 256>>>();
    // 15. out_x = x1  (ff gets atomically accumulated on top)
    copy_kernel<<<(S_ * D_ + 255) / 256, 256>>>(out_x, X1, S_ * D_);
    // 16. MoE up: hid = gelu(h2[tok]@W1[e] + b1[e])
    sgemm_kernel<1><<<gemm_grid(S_, DFF_, E_), 256>>>(H2, W1, HID, S_, DFF_, D_, b1, EL, nullptr, EC);
    // 17. MoE down: out_x[tok] += gate * (hid@W2[e] + b2[e])
    sgemm_kernel<2><<<gemm_grid(S_, D_, E_), 256>>>(HID, W2, out_x, S_, D_, DFF_, b2, EL, EG, EC);
    // 18. aux loss
    aux_kernel<<<1, 1>>>(out_aux);
}

// round 8
// speedup vs baseline: 1.5149x; 1.5149x over previous
#include <cuda_runtime.h>
#include <cuda_bf16.h>
#include <math.h>
#include <float.h>
#include <stdint.h>

// ---------------- problem constants ----------------
namespace {
constexpr int S_ = 2048, D_ = 2048, H_ = 16, DN_ = 128, DR_ = 64, DV_ = 128;
constexpr int R_ = 512, HI_ = 4, DI_ = 64, KTOP_ = 512, E_ = 4, DFF_ = 8192;
constexpr int QD  = H_ * (DN_ + DR_);   // 3072
constexpr int KVD = H_ * (DN_ + DV_);   // 4096
}

// ---------------- scratch (device globals; no allocation) ----------------
__device__ float g_h   [(size_t)S_*D_];
__device__ float g_q   [(size_t)S_*QD];
__device__ float g_ckv [(size_t)S_*(R_+DR_)];
__device__ float g_c   [(size_t)S_*R_];
__device__ float g_kv  [(size_t)S_*KVD];
__device__ float g_kr  [(size_t)S_*DR_];
__device__ float g_qi  [(size_t)S_*HI_*DI_];
__device__ float g_ki  [(size_t)S_*DI_];
__device__ float g_wgt [(size_t)S_*HI_];
__device__ float g_o   [(size_t)S_*H_*DV_];
__device__ float g_x1  [(size_t)S_*D_];
__device__ float g_h2  [(size_t)S_*D_];
__device__ float g_rlog[(size_t)S_*E_];
__device__ float g_hid [(size_t)E_*S_*DFF_];   // 256 MB MoE activations
__device__ int   g_sel   [(size_t)S_*KTOP_];
__device__ int   g_selcnt[S_];
__device__ int   g_ecnt  [E_];
__device__ int   g_elist [E_*S_];
__device__ float g_egate [E_*S_];
__device__ float g_epsum [E_];

// =====================================================================
// warp-level bf16 tensor-core helpers (portable: sm_80+, no 'a' gating)
// =====================================================================
__device__ __forceinline__ uint32_t smem_u32(const void* p) {
    uint32_t a;
    asm("{ .reg .u64 t; cvta.to.shared.u64 t, %1; cvt.u32.u64 %0, t; }" : "=r"(a) : "l"(p));
    return a;
}

__device__ __forceinline__ void ldsm_x4(uint32_t* r, uint32_t addr) {
    asm volatile("ldmatrix.sync.aligned.m8n8.x4.shared.b16 {%0,%1,%2,%3}, [%4];"
                 : "=r"(r[0]), "=r"(r[1]), "=r"(r[2]), "=r"(r[3]) : "r"(addr));
}
__device__ __forceinline__ void ldsm_x2(uint32_t* r, uint32_t addr) {
    asm volatile("ldmatrix.sync.aligned.m8n8.x2.shared.b16 {%0,%1}, [%2];"
                 : "=r"(r[0]), "=r"(r[1]) : "r"(addr));
}
__device__ __forceinline__ void mma16816(float* d, const uint32_t* a, const uint32_t* b) {
    asm volatile(
        "mma.sync.aligned.m16n8k16.row.col.f32.bf16.bf16.f32 "
        "{%0,%1,%2,%3}, {%4,%5,%6,%7}, {%8,%9}, {%0,%1,%2,%3};"
        : "+f"(d[0]), "+f"(d[1]), "+f"(d[2]), "+f"(d[3])
        : "r"(a[0]), "r"(a[1]), "r"(a[2]), "r"(a[3]), "r"(b[0]), "r"(b[1]));
}

__device__ __forceinline__ float gelu_exact(float t) {
    return 0.5f * t * (1.0f + erff(t * 0.7071067811865475f));
}

// split 8 fp32 -> bf16 hi/lo, store as 16B each (dst must be 16B aligned)
__device__ __forceinline__ void split8(const float* v, __nv_bfloat16* hi, __nv_bfloat16* lo) {
    unsigned short h[8], l[8];
#pragma unroll
    for (int i = 0; i < 8; i++) {
        __nv_bfloat16 hb = __float2bfloat16(v[i]);
        float rest = v[i] - __bfloat162float(hb);
        h[i] = __bfloat16_as_ushort(hb);
        l[i] = __bfloat16_as_ushort(__float2bfloat16(rest));
    }
    uint4 uh, ul;
    uh.x = (uint32_t)h[0] | ((uint32_t)h[1] << 16);
    uh.y = (uint32_t)h[2] | ((uint32_t)h[3] << 16);
    uh.z = (uint32_t)h[4] | ((uint32_t)h[5] << 16);
    uh.w = (uint32_t)h[6] | ((uint32_t)h[7] << 16);
    ul.x = (uint32_t)l[0] | ((uint32_t)l[1] << 16);
    ul.y = (uint32_t)l[2] | ((uint32_t)l[3] << 16);
    ul.z = (uint32_t)l[4] | ((uint32_t)l[5] << 16);
    ul.w = (uint32_t)l[6] | ((uint32_t)l[7] << 16);
    *reinterpret_cast<uint4*>(hi) = uh;
    *reinterpret_cast<uint4*>(lo) = ul;
}

// =====================================================================
// tensor-core GEMM: C[M,N] = A[M,K] @ B[K,N]  (fp32 via bf16 hi/lo split)
// MODE 0: plain   MODE 1: MoE up (gather rows, gelu+bias)
// MODE 2: MoE down (compact A rows, scatter atomicAdd gate*(acc+bias))
// MODE 3: plain + residual (extra)
// Requires: K % 32 == 0.
// 128x128 tile, BK=32, 8 warps (4m x 2n), each warp 32x64.
// =====================================================================
namespace { constexpr int TBM = 128, TBN = 128, TBK = 32, PAD = 40; }

template<int MODE>
__global__ __launch_bounds__(256)
void tgemm_kernel(const float* __restrict__ A, const float* __restrict__ Bm,
                  float* __restrict__ C, int M, int N, int K,
                  const float* __restrict__ extra,
                  const int* __restrict__ rowmap,
                  const float* __restrict__ gates,
                  const int* __restrict__ cnt) {
    __shared__ __align__(16) __nv_bfloat16 As[2][TBM][PAD];  // [hi/lo][m][k]
    __shared__ __align__(16) __nv_bfloat16 Bs[2][TBN][PAD];  // [hi/lo][n][k]

    int e = blockIdx.z;
    int Me = M;
    const float* Bp = Bm;
    const float* bias = extra;
    if (MODE == 1 || MODE == 2) {
        Me = cnt[e];
        Bp = Bm + (size_t)e * K * N;
        bias = extra + (size_t)e * N;
    }
    int row0 = blockIdx.y * TBM;
    int col0 = blockIdx.x * TBN;
    if (row0 >= Me) return;

    int tid = threadIdx.x, wid = tid >> 5, lane = tid & 31;
    int wm = wid & 3, wn = wid >> 2;          // warp tile: rows wm*32.., cols wn*64..

    float acc[2][8][4];
#pragma unroll
    for (int mi = 0; mi < 2; mi++)
#pragma unroll
        for (int ni = 0; ni < 8; ni++)
#pragma unroll
            for (int j = 0; j < 4; j++) acc[mi][ni][j] = 0.f;

    for (int k0 = 0; k0 < K; k0 += TBK) {
        // ---- stage A: 512 tasks (m fast for conflict-free smem stores)
#pragma unroll
        for (int i = 0; i < 2; i++) {
            int lin = tid + i * 256;
            int m = lin & 127, kg = lin >> 7;       // kg in 0..3
            int gm = row0 + m;
            float v[8];
            if (gm < Me) {
                const float* ap;
                if (MODE == 1)      ap = A + (size_t)rowmap[e * S_ + gm] * K;
                else if (MODE == 2) ap = A + (size_t)(e * S_ + gm) * K;
                else                ap = A + (size_t)gm * K;
                float4 f0 = *reinterpret_cast<const float4*>(ap + k0 + kg * 8);
                float4 f1 = *reinterpret_cast<const float4*>(ap + k0 + kg * 8 + 4);
                v[0]=f0.x; v[1]=f0.y; v[2]=f0.z; v[3]=f0.w;
                v[4]=f1.x; v[5]=f1.y; v[6]=f1.z; v[7]=f1.w;
            } else {
#pragma unroll
                for (int j = 0; j < 8; j++) v[j] = 0.f;
            }
            split8(v, &As[0][m][kg * 8], &As[1][m][kg * 8]);
        }
        // ---- stage B (transposed to [n][k]; loads coalesced across nn)
#pragma unroll
        for (int i = 0; i < 2; i++) {
            int lin = tid + i * 256;
            int nn = lin & 127, kg = lin >> 7;
            int gn = col0 + nn;
            float v[8];
            if (gn < N) {
                const float* bp = Bp + (size_t)(k0 + kg * 8) * N + gn;
#pragma unroll
                for (int r = 0; r < 8; r++) v[r] = bp[(size_t)r * N];
            } else {
#pragma unroll
                for (int r = 0; r < 8; r++) v[r] = 0.f;
            }
            split8(v, &Bs[0][nn][kg * 8], &Bs[1][nn][kg * 8]);
        }
        __syncthreads();

        // ---- compute: 2 k16 steps
#pragma unroll
        for (int kk = 0; kk < 2; kk++) {
            uint32_t ah[2][4], al[2][4];
            int arow = wm * 32 + (lane & 15);
            int acol = kk * 16 + (lane >> 4) * 8;
#pragma unroll
            for (int mi = 0; mi < 2; mi++) {
                ldsm_x4(ah[mi], smem_u32(&As[0][arow + mi * 16][acol]));
                ldsm_x4(al[mi], smem_u32(&As[1][arow + mi * 16][acol]));
            }
            int i16 = lane & 15;
            int brow0 = wn * 64 + (i16 & 7);
            int bcol = kk * 16 + ((i16 >> 3) & 1) * 8;
#pragma unroll
            for (int ni = 0; ni < 8; ni++) {
                uint32_t bh[2], bl[2];
                ldsm_x2(bh, smem_u32(&Bs[0][brow0 + ni * 8][bcol]));
                ldsm_x2(bl, smem_u32(&Bs[1][brow0 + ni * 8][bcol]));
#pragma unroll
                for (int mi = 0; mi < 2; mi++) {
                    mma16816(acc[mi][ni], ah[mi], bh);
                    mma16816(acc[mi][ni], ah[mi], bl);
                    mma16816(acc[mi][ni], al[mi], bh);
                }
            }
        }
        __syncthreads();
    }

    // ---- epilogue
#pragma unroll
    for (int mi = 0; mi < 2; mi++) {
        int rb = row0 + wm * 32 + mi * 16 + (lane >> 2);
        int rows[2] = {rb, rb + 8};
        int tr[2] = {0, 0}; float gate[2] = {0.f, 0.f};
        if (MODE == 2) {
#pragma unroll
            for (int j = 0; j < 2; j++) {
                if (rows[j] < Me) {
                    tr[j] = rowmap[e * S_ + rows[j]];
                    gate[j] = gates[e * S_ + rows[j]];
                }
            }
        }
#pragma unroll
        for (int ni = 0; ni < 8; ni++) {
            int c0 = col0 + wn * 64 + ni * 8 + (lane & 3) * 2;
            if (c0 >= N) continue;
#pragma unroll
            for (int j = 0; j < 2; j++) {
                int gm = rows[j];
                if (gm >= Me) continue;
                float v0 = acc[mi][ni][j * 2 + 0];
                float v1 = acc[mi][ni][j * 2 + 1];
                if (MODE == 0) {
                    C[(size_t)gm * N + c0]     = v0;
                    C[(size_t)gm * N + c0 + 1] = v1;
                } else if (MODE == 3) {
                    C[(size_t)gm * N + c0]     = v0 + extra[(size_t)gm * N + c0];
                    C[(size_t)gm * N + c0 + 1] = v1 + extra[(size_t)gm * N + c0 + 1];
                } else if (MODE == 1) {
                    C[(size_t)(e * S_ + gm) * N + c0]     = gelu_exact(v0 + bias[c0]);
                    C[(size_t)(e * S_ + gm) * N + c0 + 1] = gelu_exact(v1 + bias[c0 + 1]);
                } else { // MODE 2
                    atomicAdd(&C[(size_t)tr[j] * N + c0],     gate[j] * (v0 + bias[c0]));
                    atomicAdd(&C[(size_t)tr[j] * N + c0 + 1], gate[j] * (v1 + bias[c0 + 1]));
                }
            }
        }
    }
}

// ---------------- rmsnorm ----------------
__global__ void rms_kernel(const float* __restrict__ x, int istride,
                           const float* __restrict__ w, float* __restrict__ out, int n) {
    int row = blockIdx.x;
    const float* xr = x + (size_t)row * istride;
    __shared__ float red[256];
    float s = 0.f;
    for (int d = threadIdx.x; d < n; d += 256) { float v = xr[d]; s += v * v; }
    red[threadIdx.x] = s;
    __syncthreads();
    for (int o = 128; o > 0; o >>= 1) {
        if (threadIdx.x < o) red[threadIdx.x] += red[threadIdx.x + o];
        __syncthreads();
    }
    float scale = rsqrtf(red[0] / (float)n + 1e-6f);
    for (int d = threadIdx.x; d < n; d += 256)
        out[(size_t)row * n + d] = xr[d] * scale * w[d];
}

// ---------------- RoPE (q in-place, k_rope -> g_kr) ----------------
__global__ void rope_kernel() {
    int s = blockIdx.x;
    int tid = threadIdx.x;
    for (int t = tid; t < H_ * 32; t += blockDim.x) {
        int h = t >> 5, i = t & 31;
        float freq = powf(10000.f, -(float)i / 32.f);
        float ang = (float)s * freq;
        float cs = cosf(ang), sn = sinf(ang);
        float* p = g_q + (size_t)s * QD + h * (DN_ + DR_) + DN_;
        float a = p[i], b = p[i + 32];
        p[i]      = a * cs - b * sn;
        p[i + 32] = b * cs + a * sn;
    }
    if (tid < 32) {
        int i = tid;
        float freq = powf(10000.f, -(float)i / 32.f);
        float ang = (float)s * freq;
        float cs = cosf(ang), sn = sinf(ang);
        const float* p = g_ckv + (size_t)s * (R_ + DR_) + R_;
        float a = p[i], b = p[i + 32];
        g_kr[(size_t)s * DR_ + i]      = a * cs - b * sn;
        g_kr[(size_t)s * DR_ + i + 32] = b * cs + a * sn;
    }
}

// ---------------- indexer scores (writes masked idx_scores output) ----------------
__global__ void idx_kernel(float* __restrict__ idx_out) {
    int q = blockIdx.x;
    __shared__ float qs[HI_ * DI_];
    __shared__ float wq[HI_];
    __shared__ float kis[128 * 65];
    int tid = threadIdx.x; // 128
    for (int t = tid; t < HI_ * DI_; t += 128) qs[t] = g_qi[(size_t)q * HI_ * DI_ + t];
    if (tid < HI_) wq[tid] = g_wgt[q * HI_ + tid];
    for (int kt = 0; kt < S_; kt += 128) {
        __syncthreads();
        for (int t = tid; t < 128 * DI_; t += 128)
            kis[(t >> 6) * 65 + (t & 63)] = g_ki[(size_t)kt * DI_ + t];
        __syncthreads();
        int k = kt + tid;
        float sc;
        if (k > q) {
            sc = -FLT_MAX;
        } else {
            sc = 0.f;
            const float* krw = &kis[tid * 65];
#pragma unroll
            for (int h = 0; h < HI_; h++) {
                float d = 0.f;
#pragma unroll 8
                for (int dd = 0; dd < DI_; dd++) d += qs[h * DI_ + dd] * krw[dd];
                sc += wq[h] * fmaxf(d, 0.f);
            }
        }
        idx_out[(size_t)q * S_ + k] = sc;
    }
}

// ---------------- exact top-k (radix select, jax tie-break: smallest index) ----------------
__device__ __forceinline__ unsigned fkey(float f) {
    unsigned u = __float_as_uint(f);
    return (u & 0x80000000u) ? ~u : (u | 0x80000000u);
}

__global__ void topk_kernel(const float* __restrict__ idx_scores) {
    int q = blockIdx.x;
    int n = q + 1;
    int tid = threadIdx.x; // 256
    if (n <= KTOP_) {
        for (int k = tid; k < n; k += blockDim.x) g_sel[(size_t)q * KTOP_ + k] = k;
        if (tid == 0) g_selcnt[q] = n;
        return;
    }
    const float* row = idx_scores + (size_t)q * S_;
    __shared__ unsigned hist[256];
    __shared__ unsigned sh_prefix;
    __shared__ int sh_rem;
    __shared__ int sh_cnt;
    if (tid == 0) { sh_prefix = 0u; sh_rem = KTOP_; sh_cnt = 0; }
    __syncthreads();
    for (int p = 3; p >= 0; p--) {
        for (int b = tid; b < 256; b += blockDim.x) hist[b] = 0u;
        __syncthreads();
        unsigned pre = sh_prefix;
        int shift = 8 * (p + 1);
        for (int k = tid; k < n; k += blockDim.x) {
            unsigned u = fkey(row[k]);
            bool ok = (p == 3) || ((u >> shift) == (pre >> shift));
            if (ok) atomicAdd(&hist[(u >> (8 * p)) & 255u], 1u);
        }
        __syncthreads();
        if (tid == 0) {
            int rem = sh_rem;
            int d;
            for (d = 255; d >= 0; d--) {
                int c = (int)hist[d];
                if (c >= rem) break;
                rem -= c;
            }
            if (d < 0) d = 0;
            sh_prefix = pre | ((unsigned)d << (8 * p));
            sh_rem = rem;
        }
        __syncthreads();
    }
    unsigned T = sh_prefix;
    for (int k = tid; k < n; k += blockDim.x) {
        unsigned u = fkey(row[k]);
        if (u > T) {
            int pos = atomicAdd(&sh_cnt, 1);
            g_sel[(size_t)q * KTOP_ + pos] = k;
        }
    }
    __syncthreads();
    if (tid == 0) {
        int need = sh_rem;
        int base = sh_cnt;
        int taken = 0;
        for (int k = 0; k < n && taken < need; k++) {
            if (fkey(row[k]) == T) { g_sel[(size_t)q * KTOP_ + base + taken] = k; taken++; }
        }
        g_selcnt[q] = base + taken;   // == 512
    }
}

// ---------------- sparse attention over selected keys ----------------
__global__ void attn_kernel() {
    int s = blockIdx.x, h = blockIdx.y;
    int tid = threadIdx.x; // 128
    __shared__ float qf[DN_ + DR_];
    __shared__ float sc[KTOP_];
    __shared__ float red[128];
    for (int d = tid; d < DN_ + DR_; d += 128)
        qf[d] = g_q[(size_t)s * QD + h * (DN_ + DR_) + d];
    int cnt = g_selcnt[s];
    __syncthreads();
    int warp = tid >> 5, lane = tid & 31;
    const float scale = 0.07216878364870323f; // 1/sqrt(192)
    for (int j = warp; j < cnt; j += 4) {
        int k = g_sel[(size_t)s * KTOP_ + j];
        const float* kn = g_kv + (size_t)k * KVD + h * (DN_ + DV_);
        float p = 0.f;
        for (int d = lane; d < DN_; d += 32) p += qf[d] * kn[d];
        const float* kp = g_kr + (size_t)k * DR_;
        for (int d = lane; d < DR_; d += 32) p += qf[DN_ + d] * kp[d];
#pragma unroll
        for (int o = 16; o > 0; o >>= 1) p += __shfl_down_sync(0xffffffffu, p, o);
        if (lane == 0) sc[j] = p * scale;
    }
    __syncthreads();
    float m = -FLT_MAX;
    for (int j = tid; j < cnt; j += 128) m = fmaxf(m, sc[j]);
    red[tid] = m; __syncthreads();
    for (int o = 64; o > 0; o >>= 1) { if (tid < o) red[tid] = fmaxf(red[tid], red[tid + o]); __syncthreads(); }
    m = red[0];
    __syncthreads();
    float ssum = 0.f;
    for (int j = tid; j < cnt; j += 128) { float e = expf(sc[j] - m); sc[j] = e; ssum += e; }
    red[tid] = ssum; __syncthreads();
    for (int o = 64; o > 0; o >>= 1) { if (tid < o) red[tid] += red[tid + o]; __syncthreads(); }
    float inv = 1.f / red[0];
    __syncthreads();
    float acc = 0.f;
    for (int j = 0; j < cnt; j++) {
        int k = g_sel[(size_t)s * KTOP_ + j];
        acc += sc[j] * g_kv[(size_t)k * KVD + h * (DN_ + DV_) + DN_ + tid];
    }
    g_o[(size_t)s * (H_ * DV_) + h * DV_ + tid] = acc * inv;
}

// ---------------- router / MoE bookkeeping ----------------
__global__ void zero_small_kernel() {
    int t = threadIdx.x;
    if (t < E_) { g_ecnt[t] = 0; g_epsum[t] = 0.f; }
}

__global__ void router_kernel() {
    int t = blockIdx.x * blockDim.x + threadIdx.x;
    if (t >= S_) return;
    float l[E_];
    float m = -FLT_MAX;
#pragma unroll
    for (int e = 0; e < E_; e++) { l[e] = g_rlog[t * E_ + e]; m = fmaxf(m, l[e]); }
    float sum = 0.f;
#pragma unroll
    for (int e = 0; e < E_; e++) { l[e] = expf(l[e] - m); sum += l[e]; }
    float inv = 1.f / sum;
    float p[E_];
#pragma unroll
    for (int e = 0; e < E_; e++) { p[e] = l[e] * inv; atomicAdd(&g_epsum[e], p[e]); }
    int i0 = 0;
#pragma unroll
    for (int e = 1; e < E_; e++) if (p[e] > p[i0]) i0 = e;
    int i1 = -1;
#pragma unroll
    for (int e = 0; e < E_; e++) if (e != i0 && (i1 < 0 || p[e] > p[i1])) i1 = e;
    float g0 = p[i0], g1 = p[i1];
    float dn = g0 + g1;
    g0 /= dn; g1 /= dn;
    int s0 = atomicAdd(&g_ecnt[i0], 1);
    g_elist[i0 * S_ + s0] = t; g_egate[i0 * S_ + s0] = g0;
    int s1 = atomicAdd(&g_ecnt[i1], 1);
    g_elist[i1 * S_ + s1] = t; g_egate[i1 * S_ + s1] = g1;
}

__global__ void copy_kernel(float* __restrict__ dst, const float* __restrict__ src, int n) {
    int i = blockIdx.x * blockDim.x + threadIdx.x;
    if (i < n) dst[i] = src[i];
}

__global__ void aux_kernel(float* out) {
    float a = 0.f;
    for (int e = 0; e < E_; e++)
        a += ((float)g_ecnt[e] / (float)S_) * (g_epsum[e] / (float)S_);
    *out = (float)E_ * a;
}

// ---------------- launch ----------------
static inline dim3 tg_grid(int M, int N, int Z = 1) {
    return dim3((N + 127) / 128, (M + 127) / 128, Z);
}

extern "C" void kernel_launch(void* const* d_in, const int* in_sizes, int n_in,
                              void* d_out, int out_size) {
    const float* x        = (const float*)d_in[0];
    const float* norm1_w  = (const float*)d_in[1];
    const float* norm2_w  = (const float*)d_in[2];
    const float* kv_norm_w= (const float*)d_in[3];
    const float* Wq       = (const float*)d_in[4];
    const float* Wkva     = (const float*)d_in[5];
    const float* Wkvb     = (const float*)d_in[6];
    const float* Wo       = (const float*)d_in[7];
    const float* Wiq      = (const float*)d_in[8];
    const float* Wik      = (const float*)d_in[9];
    const float* Wiw      = (const float*)d_in[10];
    const float* Wr       = (const float*)d_in[11];
    const float* W1       = (const float*)d_in[12];
    const float* b1       = (const float*)d_in[13];
    const float* W2       = (const float*)d_in[14];
    const float* b2       = (const float*)d_in[15];

    float* out     = (float*)d_out;
    float* out_x   = out;
    float* out_aux = out + (size_t)S_ * D_;
    float* out_idx = out + (size_t)S_ * D_ + 1;

    void *ph, *pq, *pckv, *pc, *pkv, *pqi, *pki, *pwgt, *po, *px1, *ph2, *prlog, *phid,
         *pelist, *pegate, *pecnt;
    cudaGetSymbolAddress(&ph, g_h);
    cudaGetSymbolAddress(&pq, g_q);
    cudaGetSymbolAddress(&pckv, g_ckv);
    cudaGetSymbolAddress(&pc, g_c);
    cudaGetSymbolAddress(&pkv, g_kv);
    cudaGetSymbolAddress(&pqi, g_qi);
    cudaGetSymbolAddress(&pki, g_ki);
    cudaGetSymbolAddress(&pwgt, g_wgt);
    cudaGetSymbolAddress(&po, g_o);
    cudaGetSymbolAddress(&px1, g_x1);
    cudaGetSymbolAddress(&ph2, g_h2);
    cudaGetSymbolAddress(&prlog, g_rlog);
    cudaGetSymbolAddress(&phid, g_hid);
    cudaGetSymbolAddress(&pelist, g_elist);
    cudaGetSymbolAddress(&pegate, g_egate);
    cudaGetSymbolAddress(&pecnt, g_ecnt);

    float* H   = (float*)ph;
    float* Q   = (float*)pq;
    float* CKV = (float*)pckv;
    float* Cn  = (float*)pc;
    float* KV  = (float*)pkv;
    float* QI  = (float*)pqi;
    float* KI  = (float*)pki;
    float* WGT = (float*)pwgt;
    float* O   = (float*)po;
    float* X1  = (float*)px1;
    float* H2  = (float*)ph2;
    float* RL  = (float*)prlog;
    float* HID = (float*)phid;
    int*   EL  = (int*)pelist;
    float* EG  = (float*)pegate;
    int*   EC  = (int*)pecnt;

    // 1. h = rms(x, norm1_w)
    rms_kernel<<<S_, 256>>>(x, D_, norm1_w, H, D_);
    // 2. q = h@Wq
    tgemm_kernel<0><<<tg_grid(S_, QD), 256>>>(H, Wq, Q, S_, QD, D_, nullptr, nullptr, nullptr, nullptr);
    // 3. ckv = h@Wkva
    tgemm_kernel<0><<<tg_grid(S_, R_ + DR_), 256>>>(H, Wkva, CKV, S_, R_ + DR_, D_, nullptr, nullptr, nullptr, nullptr);
    // 4. indexer projections
    tgemm_kernel<0><<<tg_grid(S_, HI_ * DI_), 256>>>(H, Wiq, QI, S_, HI_ * DI_, D_, nullptr, nullptr, nullptr, nullptr);
    tgemm_kernel<0><<<tg_grid(S_, DI_), 256>>>(H, Wik, KI, S_, DI_, D_, nullptr, nullptr, nullptr, nullptr);
    tgemm_kernel<0><<<tg_grid(S_, HI_), 256>>>(H, Wiw, WGT, S_, HI_, D_, nullptr, nullptr, nullptr, nullptr);
    // 5. c = rms(ckv[:, :R], kv_norm_w)
    rms_kernel<<<S_, 256>>>(CKV, R_ + DR_, kv_norm_w, Cn, R_);
    // 6. kv = c@Wkvb
    tgemm_kernel<0><<<tg_grid(S_, KVD), 256>>>(Cn, Wkvb, KV, S_, KVD, R_, nullptr, nullptr, nullptr, nullptr);
    // 7. RoPE
    rope_kernel<<<S_, 256>>>();
    // 8. indexer scores (also output idx_scores)
    idx_kernel<<<S_, 128>>>(out_idx);
    // 9. top-k selection
    topk_kernel<<<S_, 256>>>(out_idx);
    // 10. sparse attention
    attn_kernel<<<dim3(S_, H_), 128>>>();
    // 11. x1 = o@Wo + x
    tgemm_kernel<3><<<tg_grid(S_, D_), 256>>>(O, Wo, X1, S_, D_, H_ * DV_, x, nullptr, nullptr, nullptr);
    // 12. h2 = rms(x1, norm2_w)
    rms_kernel<<<S_, 256>>>(X1, D_, norm2_w, H2, D_);
    // 13. router logits
    tgemm_kernel<0><<<tg_grid(S_, E_), 256>>>(H2, Wr, RL, S_, E_, D_, nullptr, nullptr, nullptr, nullptr);
    // 14. router: top-2, gates, per-expert lists
    zero_small_kernel<<<1, 32>>>();
    router_kernel<<<S_ / 256, 256>>>();
    // 15. out_x = x1  (ff gets atomically accumulated on top)
    copy_kernel<<<(S_ * D_ + 255) / 256, 256>>>(out_x, X1, S_ * D_);
    // 16. MoE up: hid = gelu(h2[tok]@W1[e] + b1[e])
    tgemm_kernel<1><<<tg_grid(S_, DFF_, E_), 256>>>(H2, W1, HID, S_, DFF_, D_, b1, EL, nullptr, EC);
    // 17. MoE down: out_x[tok] += gate * (hid@W2[e] + b2[e])
    tgemm_kernel<2><<<tg_grid(S_, D_, E_), 256>>>(HID, W2, out_x, S_, D_, DFF_, b2, EL, EG, EC);
    // 18. aux loss
    aux_kernel<<<1, 1>>>(out_aux);
}

// round 9
// speedup vs baseline: 1.8088x; 1.1940x over previous
#include <cuda_runtime.h>
#include <cuda_bf16.h>
#include <math.h>
#include <float.h>
#include <stdint.h>

// ---------------- problem constants ----------------
namespace {
constexpr int S_ = 2048, D_ = 2048, H_ = 16, DN_ = 128, DR_ = 64, DV_ = 128;
constexpr int R_ = 512, HI_ = 4, DI_ = 64, KTOP_ = 512, E_ = 4, DFF_ = 8192;
constexpr int QD  = H_ * (DN_ + DR_);   // 3072
}

// ---------------- scratch (device globals; no allocation) ----------------
__device__ float g_h   [(size_t)S_*D_];
__device__ float g_q   [(size_t)S_*QD];
__device__ float g_ckv [(size_t)S_*(R_+DR_)];
__device__ float g_c   [(size_t)S_*R_];
__device__ float g_kr  [(size_t)S_*DR_];
__device__ float g_qi  [(size_t)S_*HI_*DI_];
__device__ float g_ki  [(size_t)S_*DI_];
__device__ float g_wgt [(size_t)S_*HI_];
__device__ float g_qt  [(size_t)S_*H_*R_];   // 64 MB: q_nope absorbed into c-space
__device__ float g_cw  [(size_t)S_*H_*R_];   // 64 MB: attn-weighted c per head
__device__ float g_wkvbt[(size_t)H_*DN_*R_]; // 4 MB: Wkvb nope part transposed
__device__ float g_o   [(size_t)S_*H_*DV_];
__device__ float g_x1  [(size_t)S_*D_];
__device__ float g_h2  [(size_t)S_*D_];
__device__ float g_rlog[(size_t)S_*E_];
__device__ float g_hid [(size_t)E_*S_*DFF_];   // 256 MB MoE activations
__device__ int   g_sel   [(size_t)S_*KTOP_];
__device__ int   g_selcnt[S_];
__device__ int   g_ecnt  [E_];
__device__ int   g_elist [E_*S_];
__device__ float g_egate [E_*S_];
__device__ float g_epsum [E_];

// =====================================================================
// warp-level bf16 tensor-core helpers (portable: sm_80+, no 'a' gating)
// =====================================================================
__device__ __forceinline__ uint32_t smem_u32(const void* p) {
    uint32_t a;
    asm("{ .reg .u64 t; cvta.to.shared.u64 t, %1; cvt.u32.u64 %0, t; }" : "=r"(a) : "l"(p));
    return a;
}

__device__ __forceinline__ void ldsm_x4(uint32_t* r, uint32_t addr) {
    asm volatile("ldmatrix.sync.aligned.m8n8.x4.shared.b16 {%0,%1,%2,%3}, [%4];"
                 : "=r"(r[0]), "=r"(r[1]), "=r"(r[2]), "=r"(r[3]) : "r"(addr));
}
__device__ __forceinline__ void ldsm_x2(uint32_t* r, uint32_t addr) {
    asm volatile("ldmatrix.sync.aligned.m8n8.x2.shared.b16 {%0,%1}, [%2];"
                 : "=r"(r[0]), "=r"(r[1]) : "r"(addr));
}
__device__ __forceinline__ void mma16816(float* d, const uint32_t* a, const uint32_t* b) {
    asm volatile(
        "mma.sync.aligned.m16n8k16.row.col.f32.bf16.bf16.f32 "
        "{%0,%1,%2,%3}, {%4,%5,%6,%7}, {%8,%9}, {%0,%1,%2,%3};"
        : "+f"(d[0]), "+f"(d[1]), "+f"(d[2]), "+f"(d[3])
        : "r"(a[0]), "r"(a[1]), "r"(a[2]), "r"(a[3]), "r"(b[0]), "r"(b[1]));
}

__device__ __forceinline__ float gelu_exact(float t) {
    return 0.5f * t * (1.0f + erff(t * 0.7071067811865475f));
}

// split 8 fp32 -> bf16 hi/lo, store as 16B each (dst must be 16B aligned)
__device__ __forceinline__ void split8(const float* v, __nv_bfloat16* hi, __nv_bfloat16* lo) {
    unsigned short h[8], l[8];
#pragma unroll
    for (int i = 0; i < 8; i++) {
        __nv_bfloat16 hb = __float2bfloat16(v[i]);
        float rest = v[i] - __bfloat162float(hb);
        h[i] = __bfloat16_as_ushort(hb);
        l[i] = __bfloat16_as_ushort(__float2bfloat16(rest));
    }
    uint4 uh, ul;
    uh.x = (uint32_t)h[0] | ((uint32_t)h[1] << 16);
    uh.y = (uint32_t)h[2] | ((uint32_t)h[3] << 16);
    uh.z = (uint32_t)h[4] | ((uint32_t)h[5] << 16);
    uh.w = (uint32_t)h[6] | ((uint32_t)h[7] << 16);
    ul.x = (uint32_t)l[0] | ((uint32_t)l[1] << 16);
    ul.y = (uint32_t)l[2] | ((uint32_t)l[3] << 16);
    ul.z = (uint32_t)l[4] | ((uint32_t)l[5] << 16);
    ul.w = (uint32_t)l[6] | ((uint32_t)l[7] << 16);
    *reinterpret_cast<uint4*>(hi) = uh;
    *reinterpret_cast<uint4*>(lo) = ul;
}

// =====================================================================
// tensor-core GEMM: C = A @ B  (fp32 via bf16 hi/lo split, 3 terms)
// General strides lda/ldb/ldc + per-z offsets (zsA/zsB/zsC) for batched
// per-head GEMMs. MODE 0: plain  1: MoE up (gather, gelu+bias)
// 2: MoE down (compact rows, scatter atomicAdd gate*(acc+bias))  3: +residual
// Requires K % 32 == 0. 128x128 tile, BK=32, 8 warps, reg-prefetch pipeline.
// =====================================================================
namespace { constexpr int TBM = 128, TBN = 128, TBK = 32, PAD = 40; }

template<int MODE>
__global__ __launch_bounds__(256)
void tgemm_kernel(const float* __restrict__ A, const float* __restrict__ Bm,
                  float* __restrict__ C, int M, int N, int K,
                  int lda, int ldb, int ldc,
                  size_t zsA, size_t zsB, size_t zsC,
                  const float* __restrict__ extra,
                  const int* __restrict__ rowmap,
                  const float* __restrict__ gates,
                  const int* __restrict__ cnt) {
    __shared__ __align__(16) __nv_bfloat16 As[2][TBM][PAD];  // [hi/lo][m][k]
    __shared__ __align__(16) __nv_bfloat16 Bs[2][TBN][PAD];  // [hi/lo][n][k]

    int z = blockIdx.z;
    int Me = M;
    const float* Bp;
    const float* bias = nullptr;
    const float* Apz = A;
    float* Cp = C;
    if (MODE == 1 || MODE == 2) {
        Me = cnt[z];
        Bp = Bm + (size_t)z * zsB;
        bias = extra + (size_t)z * N;
    } else {
        Bp = Bm + (size_t)z * zsB;
        Apz = A + (size_t)z * zsA;
        Cp = C + (size_t)z * zsC;
    }
    int row0 = blockIdx.y * TBM;
    int col0 = blockIdx.x * TBN;
    if (row0 >= Me) return;

    int tid = threadIdx.x, wid = tid >> 5, lane = tid & 31;
    int wm = wid & 3, wn = wid >> 2;

    float acc[2][8][4];
#pragma unroll
    for (int mi = 0; mi < 2; mi++)
#pragma unroll
        for (int ni = 0; ni < 8; ni++)
#pragma unroll
            for (int j = 0; j < 4; j++) acc[mi][ni][j] = 0.f;

    float va[16], vb[16];

    auto loadA = [&](int k0, float* v) {
#pragma unroll
        for (int i = 0; i < 2; i++) {
            int lin = tid + i * 256;
            int m = lin & 127, kg = lin >> 7;
            int gm = row0 + m;
            float* d = v + i * 8;
            if (gm < Me) {
                const float* ap;
                if (MODE == 1)      ap = A + (size_t)rowmap[z * S_ + gm] * lda;
                else if (MODE == 2) ap = A + (size_t)(z * S_ + gm) * lda;
                else                ap = Apz + (size_t)gm * lda;
                float4 f0 = *reinterpret_cast<const float4*>(ap + k0 + kg * 8);
                float4 f1 = *reinterpret_cast<const float4*>(ap + k0 + kg * 8 + 4);
                d[0]=f0.x; d[1]=f0.y; d[2]=f0.z; d[3]=f0.w;
                d[4]=f1.x; d[5]=f1.y; d[6]=f1.z; d[7]=f1.w;
            } else {
#pragma unroll
                for (int j = 0; j < 8; j++) d[j] = 0.f;
            }
        }
    };
    auto loadB = [&](int k0, float* v) {
#pragma unroll
        for (int i = 0; i < 2; i++) {
            int lin = tid + i * 256;
            int nn = lin & 127, kg = lin >> 7;
            int gn = col0 + nn;
            float* d = v + i * 8;
            if (gn < N) {
                const float* bp = Bp + (size_t)(k0 + kg * 8) * ldb + gn;
#pragma unroll
                for (int r = 0; r < 8; r++) d[r] = bp[(size_t)r * ldb];
            } else {
#pragma unroll
                for (int r = 0; r < 8; r++) d[r] = 0.f;
            }
        }
    };
    auto storeAB = [&]() {
#pragma unroll
        for (int i = 0; i < 2; i++) {
            int lin = tid + i * 256;
            int m = lin & 127, kg = lin >> 7;
            split8(va + i * 8, &As[0][m][kg * 8], &As[1][m][kg * 8]);
            split8(vb + i * 8, &Bs[0][m][kg * 8], &Bs[1][m][kg * 8]);
        }
    };

    loadA(0, va);
    loadB(0, vb);

    int k0 = 0;
    while (true) {
        storeAB();
        __syncthreads();

        int kn = k0 + TBK;
        if (kn < K) {            // prefetch next tile while tensor cores run
            loadA(kn, va);
            loadB(kn, vb);
        }

        // ---- compute: 2 k16 steps
#pragma unroll
        for (int kk = 0; kk < 2; kk++) {
            uint32_t ah[2][4], al[2][4];
            int arow = wm * 32 + (lane & 15);
            int acol = kk * 16 + (lane >> 4) * 8;
#pragma unroll
            for (int mi = 0; mi < 2; mi++) {
                ldsm_x4(ah[mi], smem_u32(&As[0][arow + mi * 16][acol]));
                ldsm_x4(al[mi], smem_u32(&As[1][arow + mi * 16][acol]));
            }
            int i16 = lane & 15;
            int brow0 = wn * 64 + (i16 & 7);
            int bcol = kk * 16 + ((i16 >> 3) & 1) * 8;
#pragma unroll
            for (int ni = 0; ni < 8; ni++) {
                uint32_t bh[2], bl[2];
                ldsm_x2(bh, smem_u32(&Bs[0][brow0 + ni * 8][bcol]));
                ldsm_x2(bl, smem_u32(&Bs[1][brow0 + ni * 8][bcol]));
#pragma unroll
                for (int mi = 0; mi < 2; mi++) {
                    mma16816(acc[mi][ni], ah[mi], bh);
                    mma16816(acc[mi][ni], ah[mi], bl);
                    mma16816(acc[mi][ni], al[mi], bh);
                }
            }
        }
        __syncthreads();
        if (kn >= K) break;
        k0 = kn;
    }

    // ---- epilogue
#pragma unroll
    for (int mi = 0; mi < 2; mi++) {
        int rb = row0 + wm * 32 + mi * 16 + (lane >> 2);
        int rows[2] = {rb, rb + 8};
        int tr[2] = {0, 0}; float gate[2] = {0.f, 0.f};
        if (MODE == 2) {
#pragma unroll
            for (int j = 0; j < 2; j++) {
                if (rows[j] < Me) {
                    tr[j] = rowmap[z * S_ + rows[j]];
                    gate[j] = gates[z * S_ + rows[j]];
                }
            }
        }
#pragma unroll
        for (int ni = 0; ni < 8; ni++) {
            int c0 = col0 + wn * 64 + ni * 8 + (lane & 3) * 2;
            if (c0 >= N) continue;
#pragma unroll
            for (int j = 0; j < 2; j++) {
                int gm = rows[j];
                if (gm >= Me) continue;
                float v0 = acc[mi][ni][j * 2 + 0];
                float v1 = acc[mi][ni][j * 2 + 1];
                if (MODE == 0) {
                    Cp[(size_t)gm * ldc + c0]     = v0;
                    Cp[(size_t)gm * ldc + c0 + 1] = v1;
                } else if (MODE == 3) {
                    Cp[(size_t)gm * ldc + c0]     = v0 + extra[(size_t)gm * ldc + c0];
                    Cp[(size_t)gm * ldc + c0 + 1] = v1 + extra[(size_t)gm * ldc + c0 + 1];
                } else if (MODE == 1) {
                    C[(size_t)(z * S_ + gm) * ldc + c0]     = gelu_exact(v0 + bias[c0]);
                    C[(size_t)(z * S_ + gm) * ldc + c0 + 1] = gelu_exact(v1 + bias[c0 + 1]);
                } else { // MODE 2
                    atomicAdd(&C[(size_t)tr[j] * ldc + c0],     gate[j] * (v0 + bias[c0]));
                    atomicAdd(&C[(size_t)tr[j] * ldc + c0 + 1], gate[j] * (v1 + bias[c0 + 1]));
                }
            }
        }
    }
}

// ---------------- Wkvb nope-part transpose: g_wkvbt[h][d][r] = Wkvb[r][h*256+d]
__global__ void wkvbt_kernel(const float* __restrict__ Wkvb) {
    int idx = blockIdx.x * 256 + threadIdx.x;   // 1M total
    if (idx >= H_ * DN_ * R_) return;
    int c2 = idx & 2047;          // (h, d) fast for coalesced reads
    int h = c2 >> 7, d = c2 & 127;
    int r = idx >> 11;
    g_wkvbt[(size_t)h * DN_ * R_ + (size_t)d * R_ + r] =
        Wkvb[(size_t)r * (H_ * (DN_ + DV_)) + h * (DN_ + DV_) + d];
}

// ---------------- rmsnorm ----------------
__global__ void rms_kernel(const float* __restrict__ x, int istride,
                           const float* __restrict__ w, float* __restrict__ out, int n) {
    int row = blockIdx.x;
    const float* xr = x + (size_t)row * istride;
    __shared__ float red[256];
    float s = 0.f;
    for (int d = threadIdx.x; d < n; d += 256) { float v = xr[d]; s += v * v; }
    red[threadIdx.x] = s;
    __syncthreads();
    for (int o = 128; o > 0; o >>= 1) {
        if (threadIdx.x < o) red[threadIdx.x] += red[threadIdx.x + o];
        __syncthreads();
    }
    float scale = rsqrtf(red[0] / (float)n + 1e-6f);
    for (int d = threadIdx.x; d < n; d += 256)
        out[(size_t)row * n + d] = xr[d] * scale * w[d];
}

// ---------------- RoPE (q in-place, k_rope -> g_kr) ----------------
__global__ void rope_kernel() {
    int s = blockIdx.x;
    int tid = threadIdx.x;
    for (int t = tid; t < H_ * 32; t += blockDim.x) {
        int h = t >> 5, i = t & 31;
        float freq = powf(10000.f, -(float)i / 32.f);
        float ang = (float)s * freq;
        float cs = cosf(ang), sn = sinf(ang);
        float* p = g_q + (size_t)s * QD + h * (DN_ + DR_) + DN_;
        float a = p[i], b = p[i + 32];
        p[i]      = a * cs - b * sn;
        p[i + 32] = b * cs + a * sn;
    }
    if (tid < 32) {
        int i = tid;
        float freq = powf(10000.f, -(float)i / 32.f);
        float ang = (float)s * freq;
        float cs = cosf(ang), sn = sinf(ang);
        const float* p = g_ckv + (size_t)s * (R_ + DR_) + R_;
        float a = p[i], b = p[i + 32];
        g_kr[(size_t)s * DR_ + i]      = a * cs - b * sn;
        g_kr[(size_t)s * DR_ + i + 32] = b * cs + a * sn;
    }
}

// ---------------- indexer scores (writes masked idx_scores output) ----------------
__global__ void idx_kernel(float* __restrict__ idx_out) {
    int q = blockIdx.x;
    __shared__ float qs[HI_ * DI_];
    __shared__ float wq[HI_];
    __shared__ float kis[128 * 65];
    int tid = threadIdx.x; // 128
    for (int t = tid; t < HI_ * DI_; t += 128) qs[t] = g_qi[(size_t)q * HI_ * DI_ + t];
    if (tid < HI_) wq[tid] = g_wgt[q * HI_ + tid];
    for (int kt = 0; kt < S_; kt += 128) {
        __syncthreads();
        for (int t = tid; t < 128 * DI_; t += 128)
            kis[(t >> 6) * 65 + (t & 63)] = g_ki[(size_t)kt * DI_ + t];
        __syncthreads();
        int k = kt + tid;
        float sc;
        if (k > q) {
            sc = -FLT_MAX;
        } else {
            sc = 0.f;
            const float* krw = &kis[tid * 65];
#pragma unroll
            for (int h = 0; h < HI_; h++) {
                float d = 0.f;
#pragma unroll 8
                for (int dd = 0; dd < DI_; dd++) d += qs[h * DI_ + dd] * krw[dd];
                sc += wq[h] * fmaxf(d, 0.f);
            }
        }
        idx_out[(size_t)q * S_ + k] = sc;
    }
}

// ---------------- exact top-k (radix select, jax tie-break: smallest index) ----------------
__device__ __forceinline__ unsigned fkey(float f) {
    unsigned u = __float_as_uint(f);
    return (u & 0x80000000u) ? ~u : (u | 0x80000000u);
}

__global__ void topk_kernel(const float* __restrict__ idx_scores) {
    int q = blockIdx.x;
    int n = q + 1;
    int tid = threadIdx.x; // 256
    if (n <= KTOP_) {
        for (int k = tid; k < n; k += blockDim.x) g_sel[(size_t)q * KTOP_ + k] = k;
        if (tid == 0) g_selcnt[q] = n;
        return;
    }
    const float* row = idx_scores + (size_t)q * S_;
    __shared__ unsigned hist[256];
    __shared__ unsigned sh_prefix;
    __shared__ int sh_rem;
    __shared__ int sh_cnt;
    if (tid == 0) { sh_prefix = 0u; sh_rem = KTOP_; sh_cnt = 0; }
    __syncthreads();
    for (int p = 3; p >= 0; p--) {
        for (int b = tid; b < 256; b += blockDim.x) hist[b] = 0u;
        __syncthreads();
        unsigned pre = sh_prefix;
        int shift = 8 * (p + 1);
        for (int k = tid; k < n; k += blockDim.x) {
            unsigned u = fkey(row[k]);
            bool ok = (p == 3) || ((u >> shift) == (pre >> shift));
            if (ok) atomicAdd(&hist[(u >> (8 * p)) & 255u], 1u);
        }
        __syncthreads();
        if (tid == 0) {
            int rem = sh_rem;
            int d;
            for (d = 255; d >= 0; d--) {
                int c = (int)hist[d];
                if (c >= rem) break;
                rem -= c;
            }
            if (d < 0) d = 0;
            sh_prefix = pre | ((unsigned)d << (8 * p));
            sh_rem = rem;
        }
        __syncthreads();
    }
    unsigned T = sh_prefix;
    for (int k = tid; k < n; k += blockDim.x) {
        unsigned u = fkey(row[k]);
        if (u > T) {
            int pos = atomicAdd(&sh_cnt, 1);
            g_sel[(size_t)q * KTOP_ + pos] = k;
        }
    }
    __syncthreads();
    if (tid == 0) {
        int need = sh_rem;
        int base = sh_cnt;
        int taken = 0;
        for (int k = 0; k < n && taken < need; k++) {
            if (fkey(row[k]) == T) { g_sel[(size_t)q * KTOP_ + base + taken] = k; taken++; }
        }
        g_selcnt[q] = base + taken;   // == 512
    }
}

// ---------------- absorbed sparse attention in c-space ----------------
// block = one query s, 512 threads = 16 warps, warp w == head w.
// scores[h][j] = (q̃[s,h]·c[k_j] + q_rope[s,h]·kr[k_j]) / sqrt(192)
// g_cw[s,h] = softmax(scores[h]) weighted sum of c rows.
__global__ __launch_bounds__(512) void attn_abs_kernel() {
    int s = blockIdx.x;
    int tid = threadIdx.x;
    int h = tid >> 5, lane = tid & 31;
    __shared__ float sc[H_][KTOP_];
    __shared__ int sel_s[KTOP_];
    int cnt = g_selcnt[s];
    for (int j = tid; j < cnt; j += 512) sel_s[j] = g_sel[(size_t)s * KTOP_ + j];
    __syncthreads();

    // q̃ and q_rope in registers
    float qt[16];
#pragma unroll
    for (int i = 0; i < 16; i++)
        qt[i] = g_qt[(size_t)s * (H_ * R_) + h * R_ + lane + i * 32];
    float qr0 = g_q[(size_t)s * QD + h * (DN_ + DR_) + DN_ + lane];
    float qr1 = g_q[(size_t)s * QD + h * (DN_ + DR_) + DN_ + 32 + lane];

    const float scale = 0.07216878364870323f; // 1/sqrt(192)
    for (int j = 0; j < cnt; j++) {
        int k = sel_s[j];
        const float* cr = g_c + (size_t)k * R_;
        float p = 0.f;
#pragma unroll
        for (int i = 0; i < 16; i++) p += qt[i] * cr[lane + i * 32];
        const float* krr = g_kr + (size_t)k * DR_;
        p += qr0 * krr[lane] + qr1 * krr[lane + 32];
#pragma unroll
        for (int o = 16; o > 0; o >>= 1) p += __shfl_down_sync(0xffffffffu, p, o);
        if (lane == 0) sc[h][j] = p * scale;
    }
    __syncwarp();

    // warp-local softmax over sc[h][0..cnt)
    float m = -FLT_MAX;
    for (int j = lane; j < cnt; j += 32) m = fmaxf(m, sc[h][j]);
#pragma unroll
    for (int o = 16; o > 0; o >>= 1) m = fmaxf(m, __shfl_xor_sync(0xffffffffu, m, o));
    float ssum = 0.f;
    for (int j = lane; j < cnt; j += 32) {
        float e = expf(sc[h][j] - m);
        sc[h][j] = e;
        ssum += e;
    }
#pragma unroll
    for (int o = 16; o > 0; o >>= 1) ssum += __shfl_xor_sync(0xffffffffu, ssum, o);
    float inv = 1.f / ssum;
    __syncwarp();

    // weighted c accumulation
    float cw[16];
#pragma unroll
    for (int i = 0; i < 16; i++) cw[i] = 0.f;
    for (int j = 0; j < cnt; j++) {
        int k = sel_s[j];
        float w = sc[h][j];
        const float* cr = g_c + (size_t)k * R_;
#pragma unroll
        for (int i = 0; i < 16; i++) cw[i] += w * cr[lane + i * 32];
    }
#pragma unroll
    for (int i = 0; i < 16; i++)
        g_cw[(size_t)s * (H_ * R_) + h * R_ + lane + i * 32] = cw[i] * inv;
}

// ---------------- router / MoE bookkeeping ----------------
__global__ void zero_small_kernel() {
    int t = threadIdx.x;
    if (t < E_) { g_ecnt[t] = 0; g_epsum[t] = 0.f; }
}

__global__ void router_kernel() {
    int t = blockIdx.x * blockDim.x + threadIdx.x;
    if (t >= S_) return;
    float l[E_];
    float m = -FLT_MAX;
#pragma unroll
    for (int e = 0; e < E_; e++) { l[e] = g_rlog[t * E_ + e]; m = fmaxf(m, l[e]); }
    float sum = 0.f;
#pragma unroll
    for (int e = 0; e < E_; e++) { l[e] = expf(l[e] - m); sum += l[e]; }
    float inv = 1.f / sum;
    float p[E_];
#pragma unroll
    for (int e = 0; e < E_; e++) { p[e] = l[e] * inv; atomicAdd(&g_epsum[e], p[e]); }
    int i0 = 0;
#pragma unroll
    for (int e = 1; e < E_; e++) if (p[e] > p[i0]) i0 = e;
    int i1 = -1;
#pragma unroll
    for (int e = 0; e < E_; e++) if (e != i0 && (i1 < 0 || p[e] > p[i1])) i1 = e;
    float g0 = p[i0], g1 = p[i1];
    float dn = g0 + g1;
    g0 /= dn; g1 /= dn;
    int s0 = atomicAdd(&g_ecnt[i0], 1);
    g_elist[i0 * S_ + s0] = t; g_egate[i0 * S_ + s0] = g0;
    int s1 = atomicAdd(&g_ecnt[i1], 1);
    g_elist[i1 * S_ + s1] = t; g_egate[i1 * S_ + s1] = g1;
}

__global__ void copy_kernel(float* __restrict__ dst, const float* __restrict__ src, int n) {
    int i = blockIdx.x * blockDim.x + threadIdx.x;
    if (i < n) dst[i] = src[i];
}

__global__ void aux_kernel(float* out) {
    float a = 0.f;
    for (int e = 0; e < E_; e++)
        a += ((float)g_ecnt[e] / (float)S_) * (g_epsum[e] / (float)S_);
    *out = (float)E_ * a;
}

// ---------------- launch ----------------
static inline dim3 tg_grid(int M, int N, int Z = 1) {
    return dim3((N + 127) / 128, (M + 127) / 128, Z);
}

extern "C" void kernel_launch(void* const* d_in, const int* in_sizes, int n_in,
                              void* d_out, int out_size) {
    const float* x        = (const float*)d_in[0];
    const float* norm1_w  = (const float*)d_in[1];
    const float* norm2_w  = (const float*)d_in[2];
    const float* kv_norm_w= (const float*)d_in[3];
    const float* Wq       = (const float*)d_in[4];
    const float* Wkva     = (const float*)d_in[5];
    const float* Wkvb     = (const float*)d_in[6];
    const float* Wo       = (const float*)d_in[7];
    const float* Wiq      = (const float*)d_in[8];
    const float* Wik      = (const float*)d_in[9];
    const float* Wiw      = (const float*)d_in[10];
    const float* Wr       = (const float*)d_in[11];
    const float* W1       = (const float*)d_in[12];
    const float* b1       = (const float*)d_in[13];
    const float* W2       = (const float*)d_in[14];
    const float* b2       = (const float*)d_in[15];

    float* out     = (float*)d_out;
    float* out_x   = out;
    float* out_aux = out + (size_t)S_ * D_;
    float* out_idx = out + (size_t)S_ * D_ + 1;

    void *ph, *pq, *pckv, *pc, *pqi, *pki, *pwgt, *po, *px1, *ph2, *prlog, *phid,
         *pelist, *pegate, *pecnt, *pqt, *pcw, *pwkvbt;
    cudaGetSymbolAddress(&ph, g_h);
    cudaGetSymbolAddress(&pq, g_q);
    cudaGetSymbolAddress(&pckv, g_ckv);
    cudaGetSymbolAddress(&pc, g_c);
    cudaGetSymbolAddress(&pqi, g_qi);
    cudaGetSymbolAddress(&pki, g_ki);
    cudaGetSymbolAddress(&pwgt, g_wgt);
    cudaGetSymbolAddress(&po, g_o);
    cudaGetSymbolAddress(&px1, g_x1);
    cudaGetSymbolAddress(&ph2, g_h2);
    cudaGetSymbolAddress(&prlog, g_rlog);
    cudaGetSymbolAddress(&phid, g_hid);
    cudaGetSymbolAddress(&pelist, g_elist);
    cudaGetSymbolAddress(&pegate, g_egate);
    cudaGetSymbolAddress(&pecnt, g_ecnt);
    cudaGetSymbolAddress(&pqt, g_qt);
    cudaGetSymbolAddress(&pcw, g_cw);
    cudaGetSymbolAddress(&pwkvbt, g_wkvbt);

    float* H   = (float*)ph;
    float* Q   = (float*)pq;
    float* CKV = (float*)pckv;
    float* Cn  = (float*)pc;
    float* QI  = (float*)pqi;
    float* KI  = (float*)pki;
    float* WGT = (float*)pwgt;
    float* O   = (float*)po;
    float* X1  = (float*)px1;
    float* H2  = (float*)ph2;
    float* RL  = (float*)prlog;
    float* HID = (float*)phid;
    int*   EL  = (int*)pelist;
    float* EG  = (float*)pegate;
    int*   EC  = (int*)pecnt;
    float* QT  = (float*)pqt;
    float* CW  = (float*)pcw;
    float* WKT = (float*)pwkvbt;

    // 1. h = rms(x, norm1_w)
    rms_kernel<<<S_, 256>>>(x, D_, norm1_w, H, D_);
    // 2. q = h@Wq
    tgemm_kernel<0><<<tg_grid(S_, QD), 256>>>(H, Wq, Q, S_, QD, D_, D_, QD, QD,
                                              0, 0, 0, nullptr, nullptr, nullptr, nullptr);
    // 3. ckv = h@Wkva
    tgemm_kernel<0><<<tg_grid(S_, R_ + DR_), 256>>>(H, Wkva, CKV, S_, R_ + DR_, D_, D_, R_ + DR_, R_ + DR_,
                                                    0, 0, 0, nullptr, nullptr, nullptr, nullptr);
    // 4. indexer projections
    tgemm_kernel<0><<<tg_grid(S_, HI_ * DI_), 256>>>(H, Wiq, QI, S_, HI_ * DI_, D_, D_, HI_ * DI_, HI_ * DI_,
                                                     0, 0, 0, nullptr, nullptr, nullptr, nullptr);
    tgemm_kernel<0><<<tg_grid(S_, DI_), 256>>>(H, Wik, KI, S_, DI_, D_, D_, DI_, DI_,
                                               0, 0, 0, nullptr, nullptr, nullptr, nullptr);
    tgemm_kernel<0><<<tg_grid(S_, HI_), 256>>>(H, Wiw, WGT, S_, HI_, D_, D_, HI_, HI_,
                                               0, 0, 0, nullptr, nullptr, nullptr, nullptr);
    // 5. c = rms(ckv[:, :R], kv_norm_w)
    rms_kernel<<<S_, 256>>>(CKV, R_ + DR_, kv_norm_w, Cn, R_);
    // 6. Wkvb nope transpose (for q-absorption)
    wkvbt_kernel<<<(H_ * DN_ * R_ + 255) / 256, 256>>>(Wkvb);
    // 7. RoPE
    rope_kernel<<<S_, 256>>>();
    // 8. q̃[s,h] = q_nope[s,h] @ WkvbT[h]  (per-head batched GEMM)
    tgemm_kernel<0><<<tg_grid(S_, R_, H_), 256>>>(Q, WKT, QT, S_, R_, DN_,
                                                  QD, R_, H_ * R_,
                                                  (size_t)(DN_ + DR_), (size_t)DN_ * R_, (size_t)R_,
                                                  nullptr, nullptr, nullptr, nullptr);
    // 9. indexer scores + top-k
    idx_kernel<<<S_, 128>>>(out_idx);
    topk_kernel<<<S_, 256>>>(out_idx);
    // 10. absorbed sparse attention -> g_cw
    attn_abs_kernel<<<S_, 512>>>();
    // 11. o[s,h] = cw[s,h] @ Wkvb_v[h]  (per-head batched GEMM)
    tgemm_kernel<0><<<tg_grid(S_, DV_, H_), 256>>>(CW, Wkvb + DN_, O, S_, DV_, R_,
                                                   H_ * R_, H_ * (DN_ + DV_), H_ * DV_,
                                                   (size_t)R_, (size_t)(DN_ + DV_), (size_t)DV_,
                                                   nullptr, nullptr, nullptr, nullptr);
    // 12. x1 = o@Wo + x
    tgemm_kernel<3><<<tg_grid(S_, D_), 256>>>(O, Wo, X1, S_, D_, H_ * DV_, H_ * DV_, D_, D_,
                                              0, 0, 0, x, nullptr, nullptr, nullptr);
    // 13. h2 = rms(x1, norm2_w)
    rms_kernel<<<S_, 256>>>(X1, D_, norm2_w, H2, D_);
    // 14. router logits
    tgemm_kernel<0><<<tg_grid(S_, E_), 256>>>(H2, Wr, RL, S_, E_, D_, D_, E_, E_,
                                              0, 0, 0, nullptr, nullptr, nullptr, nullptr);
    // 15. router: top-2, gates, per-expert lists
    zero_small_kernel<<<1, 32>>>();
    router_kernel<<<S_ / 256, 256>>>();
    // 16. out_x = x1  (ff gets atomically accumulated on top)
    copy_kernel<<<(S_ * D_ + 255) / 256, 256>>>(out_x, X1, S_ * D_);
    // 17. MoE up: hid = gelu(h2[tok]@W1[e] + b1[e])
    tgemm_kernel<1><<<tg_grid(S_, DFF_, E_), 256>>>(H2, W1, HID, S_, DFF_, D_, D_, DFF_, DFF_,
                                                    0, (size_t)D_ * DFF_, 0, b1, EL, nullptr, EC);
    // 18. MoE down: out_x[tok] += gate * (hid@W2[e] + b2[e])
    tgemm_kernel<2><<<tg_grid(S_, D_, E_), 256>>>(HID, W2, out_x, S_, D_, DFF_, DFF_, D_, D_,
                                                  0, (size_t)DFF_ * D_, 0, b2, EL, EG, EC);
    // 19. aux loss
    aux_kernel<<<1, 1>>>(out_aux);
}

// round 12
// speedup vs baseline: 2.3151x; 1.2799x over previous
#include <cuda_runtime.h>
#include <cuda_bf16.h>
#include <math.h>
#include <float.h>
#include <stdint.h>

// ---------------- problem constants ----------------
namespace {
constexpr int S_ = 2048, D_ = 2048, H_ = 16, DN_ = 128, DR_ = 64, DV_ = 128;
constexpr int R_ = 512, HI_ = 4, DI_ = 64, KTOP_ = 512, E_ = 4, DFF_ = 8192;
constexpr int QD  = H_ * (DN_ + DR_);   // 3072
}

// ---------------- fp32 scratch ----------------
__device__ float g_q   [(size_t)S_*QD];
__device__ float g_ckv [(size_t)S_*(R_+DR_)];
__device__ float g_c   [(size_t)S_*R_];
__device__ float g_kr  [(size_t)S_*DR_];
__device__ float g_qi  [(size_t)S_*HI_*DI_];
__device__ float g_ki  [(size_t)S_*DI_];
__device__ float g_wgt [(size_t)S_*HI_];
__device__ float g_qt  [(size_t)S_*H_*R_];
__device__ float g_o   [(size_t)S_*H_*DV_];
__device__ float g_x1  [(size_t)S_*D_];
__device__ float g_rlog[(size_t)S_*E_];
__device__ int   g_sel   [(size_t)S_*KTOP_];
__device__ int   g_selcnt[S_];
__device__ int   g_ecnt  [E_];
__device__ int   g_elist [E_*S_];
__device__ float g_egate [E_*S_];
__device__ float g_epsum [E_];

// ---------------- bf16 hi/lo split weights (B side, [n][k] layout) ----------------
__device__ __nv_bfloat16 bWq_h  [(size_t)3072*2048], bWq_l  [(size_t)3072*2048];
__device__ __nv_bfloat16 bWkva_h[(size_t)640*2048],  bWkva_l[(size_t)640*2048];
__device__ __nv_bfloat16 bWiq_h [(size_t)256*2048],  bWiq_l [(size_t)256*2048];
__device__ __nv_bfloat16 bWik_h [(size_t)128*2048],  bWik_l [(size_t)128*2048];
__device__ __nv_bfloat16 bWiw_h [(size_t)128*2048],  bWiw_l [(size_t)128*2048];
__device__ __nv_bfloat16 bWr_h  [(size_t)128*2048],  bWr_l  [(size_t)128*2048];
__device__ __nv_bfloat16 bWkt_h [(size_t)H_*R_*DN_], bWkt_l [(size_t)H_*R_*DN_];
__device__ __nv_bfloat16 bWvv_h [(size_t)H_*DV_*R_], bWvv_l [(size_t)H_*DV_*R_];
__device__ __nv_bfloat16 bWo_h  [(size_t)2048*2048], bWo_l  [(size_t)2048*2048];
__device__ __nv_bfloat16 bW1_h  [(size_t)E_*DFF_*D_], bW1_l [(size_t)E_*DFF_*D_];
__device__ __nv_bfloat16 bW2_h  [(size_t)E_*D_*DFF_], bW2_l [(size_t)E_*D_*DFF_];
// ---------------- bf16 hi/lo split activations (A side) ----------------
__device__ __nv_bfloat16 aH_h  [(size_t)S_*D_],      aH_l  [(size_t)S_*D_];
__device__ __nv_bfloat16 aQ_h  [(size_t)S_*QD],      aQ_l  [(size_t)S_*QD];
__device__ __nv_bfloat16 aCW_h [(size_t)S_*H_*R_],   aCW_l [(size_t)S_*H_*R_];
__device__ __nv_bfloat16 aO_h  [(size_t)S_*H_*DV_],  aO_l  [(size_t)S_*H_*DV_];
__device__ __nv_bfloat16 aH2_h [(size_t)S_*D_],      aH2_l [(size_t)S_*D_];
__device__ __nv_bfloat16 aHID_h[(size_t)E_*S_*DFF_], aHID_l[(size_t)E_*S_*DFF_];

// =====================================================================
// helpers
// =====================================================================
__device__ __forceinline__ uint32_t smem_u32(const void* p) {
    uint32_t a;
    asm("{ .reg .u64 t; cvta.to.shared.u64 t, %1; cvt.u32.u64 %0, t; }" : "=r"(a) : "l"(p));
    return a;
}
__device__ __forceinline__ void ldsm_x4(uint32_t* r, uint32_t addr) {
    asm volatile("ldmatrix.sync.aligned.m8n8.x4.shared.b16 {%0,%1,%2,%3}, [%4];"
                 : "=r"(r[0]), "=r"(r[1]), "=r"(r[2]), "=r"(r[3]) : "r"(addr));
}
__device__ __forceinline__ void ldsm_x2(uint32_t* r, uint32_t addr) {
    asm volatile("ldmatrix.sync.aligned.m8n8.x2.shared.b16 {%0,%1}, [%2];"
                 : "=r"(r[0]), "=r"(r[1]) : "r"(addr));
}
__device__ __forceinline__ void mma16816(float* d, const uint32_t* a, const uint32_t* b) {
    asm volatile(
        "mma.sync.aligned.m16n8k16.row.col.f32.bf16.bf16.f32 "
        "{%0,%1,%2,%3}, {%4,%5,%6,%7}, {%8,%9}, {%0,%1,%2,%3};"
        : "+f"(d[0]), "+f"(d[1]), "+f"(d[2]), "+f"(d[3])
        : "r"(a[0]), "r"(a[1]), "r"(a[2]), "r"(a[3]), "r"(b[0]), "r"(b[1]));
}
#define CP16(dst, src, sz) asm volatile("cp.async.cg.shared.global [%0], [%1], 16, %2;" :: "r"(dst), "l"(src), "r"(sz))
#define CPCOMMIT() asm volatile("cp.async.commit_group;")
#define CPWAIT0()  asm volatile("cp.async.wait_group 0;")
#define CPWAIT1()  asm volatile("cp.async.wait_group 1;")

__device__ __forceinline__ float gelu_exact(float t) {
    return 0.5f * t * (1.0f + erff(t * 0.7071067811865475f));
}
__device__ __forceinline__ void st_split(__nv_bfloat16* h, __nv_bfloat16* l, size_t ix, float v) {
    __nv_bfloat16 hb = __float2bfloat16(v);
    h[ix] = hb;
    l[ix] = __float2bfloat16(v - __bfloat162float(hb));
}

// =====================================================================
// prep kernels: split (+transpose) into bf16 hi/lo
// =====================================================================
// tiled transpose+split: out[z][n][k] = in[z*zsIn + k*ldin + n]; n>=N zero-filled
__global__ void tsplit_kernel(const float* __restrict__ in, int ldin, size_t zsIn,
                              int K, int N,
                              __nv_bfloat16* __restrict__ oh, __nv_bfloat16* __restrict__ ol,
                              size_t zsOut) {
    __shared__ float t[32][33];
    int k0 = blockIdx.x * 32, n0 = blockIdx.y * 32, z = blockIdx.z;
    const float* ip = in + (size_t)z * zsIn;
    int tx = threadIdx.x, ty = threadIdx.y;  // 32x8
#pragma unroll
    for (int i = 0; i < 4; i++) {
        int k = k0 + ty + i * 8, n = n0 + tx;
        float v = 0.f;
        if (n < N) v = ip[(size_t)k * ldin + n];
        t[ty + i * 8][tx] = v;
    }
    __syncthreads();
    size_t ob = (size_t)z * zsOut;
#pragma unroll
    for (int i = 0; i < 4; i++) {
        int n = n0 + ty + i * 8, k = k0 + tx;
        st_split(oh, ol, ob + (size_t)n * K + k, t[tx][ty + i * 8]);
    }
}

// q-absorption B: bWkt[h][r][d] = Wkvb[r][h*256+d]  (both sides coalesced in d)
__global__ void wktsplit_kernel(const float* __restrict__ Wkvb,
                                __nv_bfloat16* __restrict__ oh, __nv_bfloat16* __restrict__ ol) {
    int idx = blockIdx.x * 256 + threadIdx.x;
    if (idx >= H_ * R_ * DN_) return;
    int d = idx & 127, r = (idx >> 7) & 511, h = idx >> 16;
    float v = Wkvb[(size_t)r * (H_ * (DN_ + DV_)) + h * (DN_ + DV_) + d];
    st_split(oh, ol, ((size_t)h * R_ + r) * DN_ + d, v);
}

// =====================================================================
// GEMM v2: bf16 hi/lo operands, cp.async double-buffer, HMMA
// =====================================================================
namespace { constexpr int TBM = 128, TBN = 128, TBK = 32, PAD = 40;
            constexpr int TGSM = 2 * 4 * 128 * PAD * 2; }   // 81920 B

template<int MODE, bool WS>
__global__ __launch_bounds__(256, 2)
void tgemm2(const __nv_bfloat16* __restrict__ Ah, const __nv_bfloat16* __restrict__ Al,
            int lda, size_t zsA,
            const __nv_bfloat16* __restrict__ Bh, const __nv_bfloat16* __restrict__ Bl,
            size_t zsB,
            float* __restrict__ C, int ldc, size_t zsC,
            __nv_bfloat16* __restrict__ Ch, __nv_bfloat16* __restrict__ Cl,
            int M, int N, int K,
            const float* __restrict__ extra, const int* __restrict__ rowmap,
            const float* __restrict__ gates, const int* __restrict__ cnt) {
    extern __shared__ __align__(16) char dynsm[];
    int z = blockIdx.z;
    int Me = M;
    const float* bias = extra;
    if (MODE == 1 || MODE == 2) {
        Me = cnt[z];
        bias = extra + (size_t)z * N;
    }
    int row0 = blockIdx.y * TBM;
    int col0 = blockIdx.x * TBN;
    if (row0 >= Me) return;

    int tid = threadIdx.x, wid = tid >> 5, lane = tid & 31;
    int wm = wid & 3, wn = wid >> 2;
    uint32_t sb = smem_u32(dynsm);

    auto smaddr = [&](int buf, int mat, int row, int col) -> uint32_t {
        return sb + (uint32_t)(((((buf << 2) + mat) << 7) + row) * PAD + col) * 2u;
    };

    float acc[2][8][4];
#pragma unroll
    for (int mi = 0; mi < 2; mi++)
#pragma unroll
        for (int ni = 0; ni < 8; ni++)
#pragma unroll
            for (int j = 0; j < 4; j++) acc[mi][ni][j] = 0.f;

    auto stage_load = [&](int buf, int k0) {
#pragma unroll
        for (int i = 0; i < 2; i++) {
            int id = tid + i * 256;        // 0..511
            int rr = id >> 2, kc = id & 3;
            int gm = row0 + rr;
            bool p = (gm < Me);
            size_t aoff;
            if (MODE == 1)      { int ar = p ? rowmap[z * S_ + gm] : 0; aoff = (size_t)ar * lda; }
            else if (MODE == 2) { aoff = (size_t)(z * S_ + gm) * lda; }
            else                { aoff = (size_t)z * zsA + (size_t)gm * lda; }
            int sz = p ? 16 : 0;
            CP16(smaddr(buf, 0, rr, kc * 8), Ah + aoff + k0 + kc * 8, sz);
            CP16(smaddr(buf, 1, rr, kc * 8), Al + aoff + k0 + kc * 8, sz);
            size_t boff = (size_t)z * zsB + (size_t)(col0 + rr) * K + k0 + kc * 8;
            CP16(smaddr(buf, 2, rr, kc * 8), Bh + boff, 16);
            CP16(smaddr(buf, 3, rr, kc * 8), Bl + boff, 16);
        }
    };

    auto compute = [&](int buf) {
#pragma unroll
        for (int kk = 0; kk < 2; kk++) {
            uint32_t ah[2][4], al[2][4];
            int arow = wm * 32 + (lane & 15);
            int acol = kk * 16 + (lane >> 4) * 8;
#pragma unroll
            for (int mi = 0; mi < 2; mi++) {
                ldsm_x4(ah[mi], smaddr(buf, 0, arow + mi * 16, acol));
                ldsm_x4(al[mi], smaddr(buf, 1, arow + mi * 16, acol));
            }
            int i16 = lane & 15;
            int brow0 = wn * 64 + (i16 & 7);
            int bcol = kk * 16 + ((i16 >> 3) & 1) * 8;
#pragma unroll
            for (int ni = 0; ni < 8; ni++) {
                uint32_t bh[2], bl[2];
                ldsm_x2(bh, smaddr(buf, 2, brow0 + ni * 8, bcol));
                ldsm_x2(bl, smaddr(buf, 3, brow0 + ni * 8, bcol));
#pragma unroll
                for (int mi = 0; mi < 2; mi++) {
                    mma16816(acc[mi][ni], ah[mi], bh);
                    mma16816(acc[mi][ni], ah[mi], bl);
                    mma16816(acc[mi][ni], al[mi], bh);
                }
            }
        }
    };

    int nt = K / TBK;
    stage_load(0, 0);
    CPCOMMIT();
    for (int t = 0; t < nt; t++) {
        if (t + 1 < nt) {
            stage_load((t + 1) & 1, (t + 1) * TBK);
            CPCOMMIT();
            CPWAIT1();
        } else {
            CPWAIT0();
        }
        __syncthreads();
        compute(t & 1);
        __syncthreads();
    }

    // ---- epilogue
#pragma unroll
    for (int mi = 0; mi < 2; mi++) {
        int rb = row0 + wm * 32 + mi * 16 + (lane >> 2);
        int rows[2] = {rb, rb + 8};
        int tr[2] = {0, 0}; float gate[2] = {0.f, 0.f};
        if (MODE == 2) {
#pragma unroll
            for (int j = 0; j < 2; j++) {
                if (rows[j] < Me) {
                    tr[j] = rowmap[z * S_ + rows[j]];
                    gate[j] = gates[z * S_ + rows[j]];
                }
            }
        }
#pragma unroll
        for (int ni = 0; ni < 8; ni++) {
            int c0 = col0 + wn * 64 + ni * 8 + (lane & 3) * 2;
            if (c0 >= N) continue;
#pragma unroll
            for (int j = 0; j < 2; j++) {
                int gm = rows[j];
                if (gm >= Me) continue;
                float v0 = acc[mi][ni][j * 2 + 0];
                float v1 = acc[mi][ni][j * 2 + 1];
                if (MODE == 0) {
                    size_t ix = (size_t)z * zsC + (size_t)gm * ldc + c0;
                    C[ix] = v0; C[ix + 1] = v1;
                    if (WS) { st_split(Ch, Cl, ix, v0); st_split(Ch, Cl, ix + 1, v1); }
                } else if (MODE == 3) {
                    size_t ix = (size_t)gm * ldc + c0;
                    C[ix]     = v0 + extra[ix];
                    C[ix + 1] = v1 + extra[ix + 1];
                } else if (MODE == 1) {
                    size_t ix = (size_t)(z * S_ + gm) * ldc + c0;
                    st_split(Ch, Cl, ix,     gelu_exact(v0 + bias[c0]));
                    st_split(Ch, Cl, ix + 1, gelu_exact(v1 + bias[c0 + 1]));
                } else { // MODE 2
                    atomicAdd(&C[(size_t)tr[j] * ldc + c0],     gate[j] * (v0 + bias[c0]));
                    atomicAdd(&C[(size_t)tr[j] * ldc + c0 + 1], gate[j] * (v1 + bias[c0 + 1]));
                }
            }
        }
    }
}

// ---------------- rmsnorm (fp32 out) ----------------
__global__ void rms_kernel(const float* __restrict__ x, int istride,
                           const float* __restrict__ w, float* __restrict__ out, int n) {
    int row = blockIdx.x;
    const float* xr = x + (size_t)row * istride;
    __shared__ float red[256];
    float s = 0.f;
    for (int d = threadIdx.x; d < n; d += 256) { float v = xr[d]; s += v * v; }
    red[threadIdx.x] = s;
    __syncthreads();
    for (int o = 128; o > 0; o >>= 1) {
        if (threadIdx.x < o) red[threadIdx.x] += red[threadIdx.x + o];
        __syncthreads();
    }
    float scale = rsqrtf(red[0] / (float)n + 1e-6f);
    for (int d = threadIdx.x; d < n; d += 256)
        out[(size_t)row * n + d] = xr[d] * scale * w[d];
}

// ---------------- rmsnorm (split bf16 out) ----------------
__global__ void rms_split_kernel(const float* __restrict__ x, int istride,
                                 const float* __restrict__ w,
                                 __nv_bfloat16* __restrict__ oh, __nv_bfloat16* __restrict__ ol,
                                 int n) {
    int row = blockIdx.x;
    const float* xr = x + (size_t)row * istride;
    __shared__ float red[256];
    float s = 0.f;
    for (int d = threadIdx.x; d < n; d += 256) { float v = xr[d]; s += v * v; }
    red[threadIdx.x] = s;
    __syncthreads();
    for (int o = 128; o > 0; o >>= 1) {
        if (threadIdx.x < o) red[threadIdx.x] += red[threadIdx.x + o];
        __syncthreads();
    }
    float scale = rsqrtf(red[0] / (float)n + 1e-6f);
    for (int d = threadIdx.x; d < n; d += 256)
        st_split(oh, ol, (size_t)row * n + d, xr[d] * scale * w[d]);
}

// ---------------- RoPE ----------------
__global__ void rope_kernel() {
    int s = blockIdx.x;
    int tid = threadIdx.x;
    for (int t = tid; t < H_ * 32; t += blockDim.x) {
        int h = t >> 5, i = t & 31;
        float freq = powf(10000.f, -(float)i / 32.f);
        float ang = (float)s * freq;
        float cs = cosf(ang), sn = sinf(ang);
        float* p = g_q + (size_t)s * QD + h * (DN_ + DR_) + DN_;
        float a = p[i], b = p[i + 32];
        p[i]      = a * cs - b * sn;
        p[i + 32] = b * cs + a * sn;
    }
    if (tid < 32) {
        int i = tid;
        float freq = powf(10000.f, -(float)i / 32.f);
        float ang = (float)s * freq;
        float cs = cosf(ang), sn = sinf(ang);
        const float* p = g_ckv + (size_t)s * (R_ + DR_) + R_;
        float a = p[i], b = p[i + 32];
        g_kr[(size_t)s * DR_ + i]      = a * cs - b * sn;
        g_kr[(size_t)s * DR_ + i + 32] = b * cs + a * sn;
    }
}

// ---------------- indexer scores ----------------
__global__ void idx_kernel(float* __restrict__ idx_out) {
    int q = blockIdx.x;
    __shared__ float qs[HI_ * DI_];
    __shared__ float wq[HI_];
    __shared__ float kis[128 * 65];
    int tid = threadIdx.x; // 128
    for (int t = tid; t < HI_ * DI_; t += 128) qs[t] = g_qi[(size_t)q * HI_ * DI_ + t];
    if (tid < HI_) wq[tid] = g_wgt[q * HI_ + tid];
    for (int kt = 0; kt < S_; kt += 128) {
        __syncthreads();
        for (int t = tid; t < 128 * DI_; t += 128)
            kis[(t >> 6) * 65 + (t & 63)] = g_ki[(size_t)kt * DI_ + t];
        __syncthreads();
        int k = kt + tid;
        float sc;
        if (k > q) {
            sc = -FLT_MAX;
        } else {
            sc = 0.f;
            const float* krw = &kis[tid * 65];
#pragma unroll
            for (int h = 0; h < HI_; h++) {
                float d = 0.f;
#pragma unroll 8
                for (int dd = 0; dd < DI_; dd++) d += qs[h * DI_ + dd] * krw[dd];
                sc += wq[h] * fmaxf(d, 0.f);
            }
        }
        idx_out[(size_t)q * S_ + k] = sc;
    }
}

// ---------------- exact top-k ----------------
__device__ __forceinline__ unsigned fkey(float f) {
    unsigned u = __float_as_uint(f);
    return (u & 0x80000000u) ? ~u : (u | 0x80000000u);
}

__global__ void topk_kernel(const float* __restrict__ idx_scores) {
    int q = blockIdx.x;
    int n = q + 1;
    int tid = threadIdx.x; // 256
    if (n <= KTOP_) {
        for (int k = tid; k < n; k += blockDim.x) g_sel[(size_t)q * KTOP_ + k] = k;
        if (tid == 0) g_selcnt[q] = n;
        return;
    }
    const float* row = idx_scores + (size_t)q * S_;
    __shared__ unsigned hist[256];
    __shared__ unsigned sh_prefix;
    __shared__ int sh_rem;
    __shared__ int sh_cnt;
    if (tid == 0) { sh_prefix = 0u; sh_rem = KTOP_; sh_cnt = 0; }
    __syncthreads();
    for (int p = 3; p >= 0; p--) {
        for (int b = tid; b < 256; b += blockDim.x) hist[b] = 0u;
        __syncthreads();
        unsigned pre = sh_prefix;
        int shift = 8 * (p + 1);
        for (int k = tid; k < n; k += blockDim.x) {
            unsigned u = fkey(row[k]);
            bool ok = (p == 3) || ((u >> shift) == (pre >> shift));
            if (ok) atomicAdd(&hist[(u >> (8 * p)) & 255u], 1u);
        }
        __syncthreads();
        if (tid == 0) {
            int rem = sh_rem;
            int d;
            for (d = 255; d >= 0; d--) {
                int c = (int)hist[d];
                if (c >= rem) break;
                rem -= c;
            }
            if (d < 0) d = 0;
            sh_prefix = pre | ((unsigned)d << (8 * p));
            sh_rem = rem;
        }
        __syncthreads();
    }
    unsigned T = sh_prefix;
    for (int k = tid; k < n; k += blockDim.x) {
        unsigned u = fkey(row[k]);
        if (u > T) {
            int pos = atomicAdd(&sh_cnt, 1);
            g_sel[(size_t)q * KTOP_ + pos] = k;
        }
    }
    __syncthreads();
    if (tid == 0) {
        int need = sh_rem;
        int base = sh_cnt;
        int taken = 0;
        for (int k = 0; k < n && taken < need; k++) {
            if (fkey(row[k]) == T) { g_sel[(size_t)q * KTOP_ + base + taken] = k; taken++; }
        }
        g_selcnt[q] = base + taken;   // == 512
    }
}

// ---------------- absorbed sparse attention in c-space ----------------
__global__ __launch_bounds__(512) void attn_abs_kernel() {
    int s = blockIdx.x;
    int tid = threadIdx.x;
    int h = tid >> 5, lane = tid & 31;
    __shared__ float sc[H_][KTOP_];
    __shared__ int sel_s[KTOP_];
    int cnt = g_selcnt[s];
    for (int j = tid; j < cnt; j += 512) sel_s[j] = g_sel[(size_t)s * KTOP_ + j];
    __syncthreads();

    float qt[16];
#pragma unroll
    for (int i = 0; i < 16; i++)
        qt[i] = g_qt[(size_t)s * (H_ * R_) + h * R_ + lane + i * 32];
    float qr0 = g_q[(size_t)s * QD + h * (DN_ + DR_) + DN_ + lane];
    float qr1 = g_q[(size_t)s * QD + h * (DN_ + DR_) + DN_ + 32 + lane];

    const float scale = 0.07216878364870323f; // 1/sqrt(192)
    for (int j = 0; j < cnt; j++) {
        int k = sel_s[j];
        const float* cr = g_c + (size_t)k * R_;
        float p = 0.f;
#pragma unroll
        for (int i = 0; i < 16; i++) p += qt[i] * cr[lane + i * 32];
        const float* krr = g_kr + (size_t)k * DR_;
        p += qr0 * krr[lane] + qr1 * krr[lane + 32];
#pragma unroll
        for (int o = 16; o > 0; o >>= 1) p += __shfl_down_sync(0xffffffffu, p, o);
        if (lane == 0) sc[h][j] = p * scale;
    }
    __syncwarp();

    float m = -FLT_MAX;
    for (int j = lane; j < cnt; j += 32) m = fmaxf(m, sc[h][j]);
#pragma unroll
    for (int o = 16; o > 0; o >>= 1) m = fmaxf(m, __shfl_xor_sync(0xffffffffu, m, o));
    float ssum = 0.f;
    for (int j = lane; j < cnt; j += 32) {
        float e = expf(sc[h][j] - m);
        sc[h][j] = e;
        ssum += e;
    }
#pragma unroll
    for (int o = 16; o > 0; o >>= 1) ssum += __shfl_xor_sync(0xffffffffu, ssum, o);
    float inv = 1.f / ssum;
    __syncwarp();

    float cw[16];
#pragma unroll
    for (int i = 0; i < 16; i++) cw[i] = 0.f;
    for (int j = 0; j < cnt; j++) {
        int k = sel_s[j];
        float w = sc[h][j];
        const float* cr = g_c + (size_t)k * R_;
#pragma unroll
        for (int i = 0; i < 16; i++) cw[i] += w * cr[lane + i * 32];
    }
#pragma unroll
    for (int i = 0; i < 16; i++)
        st_split(aCW_h, aCW_l, (size_t)s * (H_ * R_) + h * R_ + lane + i * 32, cw[i] * inv);
}

// ---------------- router / MoE bookkeeping ----------------
__global__ void zero_small_kernel() {
    int t = threadIdx.x;
    if (t < E_) { g_ecnt[t] = 0; g_epsum[t] = 0.f; }
}

__global__ void router_kernel() {
    int t = blockIdx.x * blockDim.x + threadIdx.x;
    if (t >= S_) return;
    float l[E_];
    float m = -FLT_MAX;
#pragma unroll
    for (int e = 0; e < E_; e++) { l[e] = g_rlog[t * E_ + e]; m = fmaxf(m, l[e]); }
    float sum = 0.f;
#pragma unroll
    for (int e = 0; e < E_; e++) { l[e] = expf(l[e] - m); sum += l[e]; }
    float inv = 1.f / sum;
    float p[E_];
#pragma unroll
    for (int e = 0; e < E_; e++) { p[e] = l[e] * inv; atomicAdd(&g_epsum[e], p[e]); }
    int i0 = 0;
#pragma unroll
    for (int e = 1; e < E_; e++) if (p[e] > p[i0]) i0 = e;
    int i1 = -1;
#pragma unroll
    for (int e = 0; e < E_; e++) if (e != i0 && (i1 < 0 || p[e] > p[i1])) i1 = e;
    float g0 = p[i0], g1 = p[i1];
    float dn = g0 + g1;
    g0 /= dn; g1 /= dn;
    int s0 = atomicAdd(&g_ecnt[i0], 1);
    g_elist[i0 * S_ + s0] = t; g_egate[i0 * S_ + s0] = g0;
    int s1 = atomicAdd(&g_ecnt[i1], 1);
    g_elist[i1 * S_ + s1] = t; g_egate[i1 * S_ + s1] = g1;
}

__global__ void copy_kernel(float* __restrict__ dst, const float* __restrict__ src, int n) {
    int i = blockIdx.x * blockDim.x + threadIdx.x;
    if (i < n) dst[i] = src[i];
}

__global__ void aux_kernel(float* out) {
    float a = 0.f;
    for (int e = 0; e < E_; e++)
        a += ((float)g_ecnt[e] / (float)S_) * (g_epsum[e] / (float)S_);
    *out = (float)E_ * a;
}

// ---------------- launch ----------------
static inline dim3 tg_grid(int M, int N, int Z = 1) {
    return dim3((N + 127) / 128, (M + 127) / 128, Z);
}

template<typename T>
static T* sym(const void* s) { void* p; cudaGetSymbolAddress(&p, s); return (T*)p; }

extern "C" void kernel_launch(void* const* d_in, const int* in_sizes, int n_in,
                              void* d_out, int out_size) {
    const float* x        = (const float*)d_in[0];
    const float* norm1_w  = (const float*)d_in[1];
    const float* norm2_w  = (const float*)d_in[2];
    const float* kv_norm_w= (const float*)d_in[3];
    const float* Wq       = (const float*)d_in[4];
    const float* Wkva     = (const float*)d_in[5];
    const float* Wkvb     = (const float*)d_in[6];
    const float* Wo       = (const float*)d_in[7];
    const float* Wiq      = (const float*)d_in[8];
    const float* Wik      = (const float*)d_in[9];
    const float* Wiw      = (const float*)d_in[10];
    const float* Wr       = (const float*)d_in[11];
    const float* W1       = (const float*)d_in[12];
    const float* b1       = (const float*)d_in[13];
    const float* W2       = (const float*)d_in[14];
    const float* b2       = (const float*)d_in[15];

    float* out     = (float*)d_out;
    float* out_x   = out;
    float* out_aux = out + (size_t)S_ * D_;
    float* out_idx = out + (size_t)S_ * D_ + 1;

    static bool attr_done = false;
    if (!attr_done) {
        cudaFuncSetAttribute(tgemm2<0, false>, cudaFuncAttributeMaxDynamicSharedMemorySize, TGSM);
        cudaFuncSetAttribute(tgemm2<0, true>,  cudaFuncAttributeMaxDynamicSharedMemorySize, TGSM);
        cudaFuncSetAttribute(tgemm2<1, true>,  cudaFuncAttributeMaxDynamicSharedMemorySize, TGSM);
        cudaFuncSetAttribute(tgemm2<2, false>, cudaFuncAttributeMaxDynamicSharedMemorySize, TGSM);
        cudaFuncSetAttribute(tgemm2<3, false>, cudaFuncAttributeMaxDynamicSharedMemorySize, TGSM);
        attr_done = true;
    }

    typedef __nv_bfloat16 bf;
    float* Q   = sym<float>(g_q);
    float* CKV = sym<float>(g_ckv);
    float* Cn  = sym<float>(g_c);
    float* QI  = sym<float>(g_qi);
    float* KI  = sym<float>(g_ki);
    float* WGT = sym<float>(g_wgt);
    float* QT  = sym<float>(g_qt);
    float* O   = sym<float>(g_o);
    float* X1  = sym<float>(g_x1);
    float* RL  = sym<float>(g_rlog);
    int*   EL  = sym<int>(g_elist);
    float* EG  = sym<float>(g_egate);
    int*   EC  = sym<int>(g_ecnt);
    bf *pWq_h = sym<bf>(bWq_h), *pWq_l = sym<bf>(bWq_l);
    bf *pWkva_h = sym<bf>(bWkva_h), *pWkva_l = sym<bf>(bWkva_l);
    bf *pWiq_h = sym<bf>(bWiq_h), *pWiq_l = sym<bf>(bWiq_l);
    bf *pWik_h = sym<bf>(bWik_h), *pWik_l = sym<bf>(bWik_l);
    bf *pWiw_h = sym<bf>(bWiw_h), *pWiw_l = sym<bf>(bWiw_l);
    bf *pWr_h = sym<bf>(bWr_h), *pWr_l = sym<bf>(bWr_l);
    bf *pWkt_h = sym<bf>(bWkt_h), *pWkt_l = sym<bf>(bWkt_l);
    bf *pWvv_h = sym<bf>(bWvv_h), *pWvv_l = sym<bf>(bWvv_l);
    bf *pWo_h = sym<bf>(bWo_h), *pWo_l = sym<bf>(bWo_l);
    bf *pW1_h = sym<bf>(bW1_h), *pW1_l = sym<bf>(bW1_l);
    bf *pW2_h = sym<bf>(bW2_h), *pW2_l = sym<bf>(bW2_l);
    bf *pH_h = sym<bf>(aH_h), *pH_l = sym<bf>(aH_l);
    bf *pQ_h = sym<bf>(aQ_h), *pQ_l = sym<bf>(aQ_l);
    bf *pO_h = sym<bf>(aO_h), *pO_l = sym<bf>(aO_l);
    bf *pH2_h = sym<bf>(aH2_h), *pH2_l = sym<bf>(aH2_l);
    bf *pCW_h = sym<bf>(aCW_h), *pCW_l = sym<bf>(aCW_l);
    bf *pHID_h = sym<bf>(aHID_h), *pHID_l = sym<bf>(aHID_l);

    dim3 tb(32, 8);
    // ---- weight prep (split + transpose to [n][k]) ----
    tsplit_kernel<<<dim3(64, 96, 1),  tb>>>(Wq,   3072, 0, 2048, 3072, pWq_h,   pWq_l,   0);
    tsplit_kernel<<<dim3(64, 20, 1),  tb>>>(Wkva, 576,  0, 2048, 576,  pWkva_h, pWkva_l, 0);
    tsplit_kernel<<<dim3(64, 8, 1),   tb>>>(Wiq,  256,  0, 2048, 256,  pWiq_h,  pWiq_l,  0);
    tsplit_kernel<<<dim3(64, 4, 1),   tb>>>(Wik,  64,   0, 2048, 64,   pWik_h,  pWik_l,  0);
    tsplit_kernel<<<dim3(64, 4, 1),   tb>>>(Wiw,  4,    0, 2048, 4,    pWiw_h,  pWiw_l,  0);
    tsplit_kernel<<<dim3(64, 4, 1),   tb>>>(Wr,   4,    0, 2048, 4,    pWr_h,   pWr_l,   0);
    // FIX (R11 bug): Wo is 2048x2048 -> grid.y must be 2048/32 = 64 (was 16,
    // leaving bWo rows 512..2047 zero and silently dropping 3/4 of o@Wo).
    tsplit_kernel<<<dim3(64, 64, 1),  tb>>>(Wo,   2048, 0, 2048, 2048, pWo_h,   pWo_l,   0);
    tsplit_kernel<<<dim3(64, 256, 4), tb>>>(W1,   8192, (size_t)D_ * DFF_, 2048, 8192, pW1_h, pW1_l, (size_t)DFF_ * D_);
    tsplit_kernel<<<dim3(256, 64, 4), tb>>>(W2,   2048, (size_t)DFF_ * D_, 8192, 2048, pW2_h, pW2_l, (size_t)D_ * DFF_);
    tsplit_kernel<<<dim3(16, 4, 16),  tb>>>(Wkvb + DN_, H_ * (DN_ + DV_), 256, 512, 128, pWvv_h, pWvv_l, (size_t)DV_ * R_);
    wktsplit_kernel<<<(H_ * R_ * DN_ + 255) / 256, 256>>>(Wkvb, pWkt_h, pWkt_l);

    // 1. h = rms(x) -> split
    rms_split_kernel<<<S_, 256>>>(x, D_, norm1_w, pH_h, pH_l, D_);
    // 2. q = h@Wq (fp32 + split)
    tgemm2<0, true><<<tg_grid(S_, QD), 256, TGSM>>>(pH_h, pH_l, D_, 0, pWq_h, pWq_l, 0,
        Q, QD, 0, pQ_h, pQ_l, S_, QD, D_, nullptr, nullptr, nullptr, nullptr);
    // 3. ckv = h@Wkva (fp32)
    tgemm2<0, false><<<tg_grid(S_, R_ + DR_), 256, TGSM>>>(pH_h, pH_l, D_, 0, pWkva_h, pWkva_l, 0,
        CKV, R_ + DR_, 0, nullptr, nullptr, S_, R_ + DR_, D_, nullptr, nullptr, nullptr, nullptr);
    // 4. indexer projections (fp32)
    tgemm2<0, false><<<tg_grid(S_, HI_ * DI_), 256, TGSM>>>(pH_h, pH_l, D_, 0, pWiq_h, pWiq_l, 0,
        QI, HI_ * DI_, 0, nullptr, nullptr, S_, HI_ * DI_, D_, nullptr, nullptr, nullptr, nullptr);
    tgemm2<0, false><<<tg_grid(S_, DI_), 256, TGSM>>>(pH_h, pH_l, D_, 0, pWik_h, pWik_l, 0,
        KI, DI_, 0, nullptr, nullptr, S_, DI_, D_, nullptr, nullptr, nullptr, nullptr);
    tgemm2<0, false><<<tg_grid(S_, HI_), 256, TGSM>>>(pH_h, pH_l, D_, 0, pWiw_h, pWiw_l, 0,
        WGT, HI_, 0, nullptr, nullptr, S_, HI_, D_, nullptr, nullptr, nullptr, nullptr);
    // 5. c = rms(ckv[:, :R]) fp32
    rms_kernel<<<S_, 256>>>(CKV, R_ + DR_, kv_norm_w, Cn, R_);
    // 6. RoPE
    rope_kernel<<<S_, 256>>>();
    // 7. q̃ = q_nope @ WkvbT (per-head)
    tgemm2<0, false><<<tg_grid(S_, R_, H_), 256, TGSM>>>(pQ_h, pQ_l, QD, (size_t)(DN_ + DR_),
        pWkt_h, pWkt_l, (size_t)R_ * DN_,
        QT, H_ * R_, (size_t)R_, nullptr, nullptr, S_, R_, DN_, nullptr, nullptr, nullptr, nullptr);
    // 8. indexer + top-k
    idx_kernel<<<S_, 128>>>(out_idx);
    topk_kernel<<<S_, 256>>>(out_idx);
    // 9. absorbed sparse attention -> cw split
    attn_abs_kernel<<<S_, 512>>>();
    // 10. o = cw @ Wkvb_v (per-head, fp32 + split)
    tgemm2<0, true><<<tg_grid(S_, DV_, H_), 256, TGSM>>>(pCW_h, pCW_l, H_ * R_, (size_t)R_,
        pWvv_h, pWvv_l, (size_t)DV_ * R_,
        O, H_ * DV_, (size_t)DV_, pO_h, pO_l, S_, DV_, R_, nullptr, nullptr, nullptr, nullptr);
    // 11. x1 = o@Wo + x
    tgemm2<3, false><<<tg_grid(S_, D_), 256, TGSM>>>(pO_h, pO_l, H_ * DV_, 0, pWo_h, pWo_l, 0,
        X1, D_, 0, nullptr, nullptr, S_, D_, H_ * DV_, x, nullptr, nullptr, nullptr);
    // 12. h2 = rms(x1) -> split
    rms_split_kernel<<<S_, 256>>>(X1, D_, norm2_w, pH2_h, pH2_l, D_);
    // 13. router logits
    tgemm2<0, false><<<tg_grid(S_, E_), 256, TGSM>>>(pH2_h, pH2_l, D_, 0, pWr_h, pWr_l, 0,
        RL, E_, 0, nullptr, nullptr, S_, E_, D_, nullptr, nullptr, nullptr, nullptr);
    // 14. router
    zero_small_kernel<<<1, 32>>>();
    router_kernel<<<S_ / 256, 256>>>();
    // 15. out_x = x1
    copy_kernel<<<(S_ * D_ + 255) / 256, 256>>>(out_x, X1, S_ * D_);
    // 16. MoE up: hid(split) = gelu(h2[tok]@W1[e] + b1[e])
    tgemm2<1, true><<<tg_grid(S_, DFF_, E_), 256, TGSM>>>(pH2_h, pH2_l, D_, 0,
        pW1_h, pW1_l, (size_t)DFF_ * D_,
        nullptr, DFF_, 0, pHID_h, pHID_l, S_, DFF_, D_, b1, EL, nullptr, EC);
    // 17. MoE down: out_x[tok] += gate*(hid@W2[e] + b2[e])
    tgemm2<2, false><<<tg_grid(S_, D_, E_), 256, TGSM>>>(pHID_h, pHID_l, DFF_, 0,
        pW2_h, pW2_l, (size_t)D_ * DFF_,
        out_x, D_, 0, nullptr, nullptr, S_, D_, DFF_, b2, EL, EG, EC);
    // 18. aux
    aux_kernel<<<1, 1>>>(out_aux);
}

// round 13
// speedup vs baseline: 2.3659x; 1.0219x over previous
#include <cuda_runtime.h>
#include <cuda_bf16.h>
#include <math.h>
#include <float.h>
#include <stdint.h>

// ---------------- problem constants ----------------
namespace {
constexpr int S_ = 2048, D_ = 2048, H_ = 16, DN_ = 128, DR_ = 64, DV_ = 128;
constexpr int R_ = 512, HI_ = 4, DI_ = 64, KTOP_ = 512, E_ = 4, DFF_ = 8192;
constexpr int QD  = H_ * (DN_ + DR_);   // 3072
// fused h-projection layout (columns)
constexpr int FN   = 4096;              // padded fused width
constexpr int FQO  = 0;                 // q:    cols [0, 3072)
constexpr int FCKV = 3072;              // ckv:  cols [3072, 3648)
constexpr int FQI  = 3648;              // qi:   cols [3648, 3904)
constexpr int FKI  = 3904;              // ki:   cols [3904, 3968)
constexpr int FWG  = 3968;              // wgt:  cols [3968, 3972)
constexpr int FNR  = 3972;              // real fused N
}

// ---------------- fp32 scratch ----------------
__device__ float g_f   [(size_t)S_*FN];       // fused projections (q|ckv|qi|ki|wgt)
__device__ float g_c   [(size_t)S_*R_];
__device__ float g_kr  [(size_t)S_*DR_];
__device__ float g_qt  [(size_t)S_*H_*R_];
__device__ float g_o   [(size_t)S_*H_*DV_];
__device__ float g_x1  [(size_t)S_*D_];
__device__ float g_rlog[(size_t)S_*E_];
__device__ int   g_sel   [(size_t)S_*KTOP_];
__device__ int   g_selcnt[S_];
__device__ int   g_ecnt  [E_];
__device__ int   g_elist [E_*S_];
__device__ float g_egate [E_*S_];
__device__ float g_epsum [E_];

// ---------------- bf16 hi/lo split weights (B side, [n][k] layout) ----------------
__device__ __nv_bfloat16 bWF_h  [(size_t)FN*2048],   bWF_l  [(size_t)FN*2048];   // fused Wq|Wkva|Wiq|Wik|Wiw
__device__ __nv_bfloat16 bWr_h  [(size_t)128*2048],  bWr_l  [(size_t)128*2048];
__device__ __nv_bfloat16 bWkt_h [(size_t)H_*R_*DN_], bWkt_l [(size_t)H_*R_*DN_];
__device__ __nv_bfloat16 bWvv_h [(size_t)H_*DV_*R_], bWvv_l [(size_t)H_*DV_*R_];
__device__ __nv_bfloat16 bWo_h  [(size_t)2048*2048], bWo_l  [(size_t)2048*2048];
__device__ __nv_bfloat16 bW1_h  [(size_t)E_*DFF_*D_], bW1_l [(size_t)E_*DFF_*D_];
__device__ __nv_bfloat16 bW2_h  [(size_t)E_*D_*DFF_], bW2_l [(size_t)E_*D_*DFF_];
// ---------------- bf16 hi/lo split activations (A side) ----------------
__device__ __nv_bfloat16 aH_h  [(size_t)S_*D_],      aH_l  [(size_t)S_*D_];
__device__ __nv_bfloat16 aF_h  [(size_t)S_*FN],      aF_l  [(size_t)S_*FN];
__device__ __nv_bfloat16 aCW_h [(size_t)S_*H_*R_],   aCW_l [(size_t)S_*H_*R_];
__device__ __nv_bfloat16 aO_h  [(size_t)S_*H_*DV_],  aO_l  [(size_t)S_*H_*DV_];
__device__ __nv_bfloat16 aH2_h [(size_t)S_*D_],      aH2_l [(size_t)S_*D_];
__device__ __nv_bfloat16 aHID_h[(size_t)E_*S_*DFF_], aHID_l[(size_t)E_*S_*DFF_];

// =====================================================================
// helpers
// =====================================================================
__device__ __forceinline__ uint32_t smem_u32(const void* p) {
    uint32_t a;
    asm("{ .reg .u64 t; cvta.to.shared.u64 t, %1; cvt.u32.u64 %0, t; }" : "=r"(a) : "l"(p));
    return a;
}
__device__ __forceinline__ void ldsm_x4(uint32_t* r, uint32_t addr) {
    asm volatile("ldmatrix.sync.aligned.m8n8.x4.shared.b16 {%0,%1,%2,%3}, [%4];"
                 : "=r"(r[0]), "=r"(r[1]), "=r"(r[2]), "=r"(r[3]) : "r"(addr));
}
__device__ __forceinline__ void ldsm_x2(uint32_t* r, uint32_t addr) {
    asm volatile("ldmatrix.sync.aligned.m8n8.x2.shared.b16 {%0,%1}, [%2];"
                 : "=r"(r[0]), "=r"(r[1]) : "r"(addr));
}
__device__ __forceinline__ void mma16816(float* d, const uint32_t* a, const uint32_t* b) {
    asm volatile(
        "mma.sync.aligned.m16n8k16.row.col.f32.bf16.bf16.f32 "
        "{%0,%1,%2,%3}, {%4,%5,%6,%7}, {%8,%9}, {%0,%1,%2,%3};"
        : "+f"(d[0]), "+f"(d[1]), "+f"(d[2]), "+f"(d[3])
        : "r"(a[0]), "r"(a[1]), "r"(a[2]), "r"(a[3]), "r"(b[0]), "r"(b[1]));
}
#define CP16(dst, src, sz) asm volatile("cp.async.cg.shared.global [%0], [%1], 16, %2;" :: "r"(dst), "l"(src), "r"(sz))
#define CPCOMMIT() asm volatile("cp.async.commit_group;")
#define CPWAIT0()  asm volatile("cp.async.wait_group 0;")
#define CPWAIT1()  asm volatile("cp.async.wait_group 1;")

__device__ __forceinline__ float gelu_exact(float t) {
    return 0.5f * t * (1.0f + erff(t * 0.7071067811865475f));
}
__device__ __forceinline__ void st_split(__nv_bfloat16* h, __nv_bfloat16* l, size_t ix, float v) {
    __nv_bfloat16 hb = __float2bfloat16(v);
    h[ix] = hb;
    l[ix] = __float2bfloat16(v - __bfloat162float(hb));
}

// =====================================================================
// prep kernels
// =====================================================================
// tiled transpose+split: out[z][n][k] = in[z*zsIn + k*ldin + n]; n>=N zero-filled
__global__ void tsplit_kernel(const float* __restrict__ in, int ldin, size_t zsIn,
                              int K, int N,
                              __nv_bfloat16* __restrict__ oh, __nv_bfloat16* __restrict__ ol,
                              size_t zsOut) {
    __shared__ float t[32][33];
    int k0 = blockIdx.x * 32, n0 = blockIdx.y * 32, z = blockIdx.z;
    const float* ip = in + (size_t)z * zsIn;
    int tx = threadIdx.x, ty = threadIdx.y;  // 32x8
#pragma unroll
    for (int i = 0; i < 4; i++) {
        int k = k0 + ty + i * 8, n = n0 + tx;
        float v = 0.f;
        if (n < N) v = ip[(size_t)k * ldin + n];
        t[ty + i * 8][tx] = v;
    }
    __syncthreads();
    size_t ob = (size_t)z * zsOut;
#pragma unroll
    for (int i = 0; i < 4; i++) {
        int n = n0 + ty + i * 8, k = k0 + tx;
        st_split(oh, ol, ob + (size_t)n * K + k, t[tx][ty + i * 8]);
    }
}

// q-absorption B: bWkt[h][r][d] = Wkvb[r][h*256+d]
__global__ void wktsplit_kernel(const float* __restrict__ Wkvb,
                                __nv_bfloat16* __restrict__ oh, __nv_bfloat16* __restrict__ ol) {
    int idx = blockIdx.x * 256 + threadIdx.x;
    if (idx >= H_ * R_ * DN_) return;
    int d = idx & 127, r = (idx >> 7) & 511, h = idx >> 16;
    float v = Wkvb[(size_t)r * (H_ * (DN_ + DV_)) + h * (DN_ + DV_) + d];
    st_split(oh, ol, ((size_t)h * R_ + r) * DN_ + d, v);
}

// =====================================================================
// GEMM v3: bf16 hi/lo, cp.async double-buffer, HMMA, fully hoisted addressing
// =====================================================================
namespace { constexpr int TBM = 128, TBN = 128, TBK = 32, PAD = 40;
            constexpr int MS  = 128 * PAD * 2;       // one matrix slab (10240 B)
            constexpr int BSZ = 4 * MS;              // one buffer (40960 B)
            constexpr int TGSM = 2 * BSZ; }          // 81920 B

template<int MODE, bool WS>
__global__ __launch_bounds__(256, 2)
void tgemm2(const __nv_bfloat16* __restrict__ Ah, const __nv_bfloat16* __restrict__ Al,
            int lda, size_t zsA,
            const __nv_bfloat16* __restrict__ Bh, const __nv_bfloat16* __restrict__ Bl,
            size_t zsB,
            float* __restrict__ C, int ldc, size_t zsC,
            __nv_bfloat16* __restrict__ Ch, __nv_bfloat16* __restrict__ Cl,
            int M, int N, int K,
            const float* __restrict__ extra, const int* __restrict__ rowmap,
            const float* __restrict__ gates, const int* __restrict__ cnt) {
    extern __shared__ __align__(16) char dynsm[];
    int z = blockIdx.z;
    int Me = M;
    const float* bias = extra;
    if (MODE == 1 || MODE == 2) {
        Me = cnt[z];
        bias = extra + (size_t)z * N;
    }
    int row0 = blockIdx.y * TBM;
    int col0 = blockIdx.x * TBN;
    if (row0 >= Me) return;

    int tid = threadIdx.x, wid = tid >> 5, lane = tid & 31;
    int wm = wid & 3, wn = wid >> 2;
    uint32_t sb = smem_u32(dynsm);

    // ---- hoisted stage-load state (k-independent) ----
    uint32_t dst0[2];
    const __nv_bfloat16 *pAh[2], *pAl[2], *pBh[2], *pBl[2];
    int szp[2];
#pragma unroll
    for (int i = 0; i < 2; i++) {
        int id = tid + i * 256;
        int rr = id >> 2, kc = id & 3;
        dst0[i] = sb + (uint32_t)(rr * PAD + kc * 8) * 2u;
        int gm = row0 + rr;
        bool p = (gm < Me);
        szp[i] = p ? 16 : 0;
        size_t aoff;
        if (MODE == 1)      { int ar = p ? rowmap[z * S_ + gm] : 0; aoff = (size_t)ar * lda; }
        else if (MODE == 2) { aoff = (size_t)(z * S_ + gm) * lda; }
        else                { aoff = (size_t)z * zsA + (size_t)gm * lda; }
        pAh[i] = Ah + aoff + kc * 8;
        pAl[i] = Al + aoff + kc * 8;
        size_t boff = (size_t)z * zsB + (size_t)(col0 + rr) * K + kc * 8;
        pBh[i] = Bh + boff;
        pBl[i] = Bl + boff;
    }

    // ---- hoisted fragment smem addresses (buf0) ----
    uint32_t aAddr[2][2][2];   // [kk][mi][hi/lo]
    uint32_t bAddr[2];         // [kk] Bh base
    {
        int arow = wm * 32 + (lane & 15);
        int i16 = lane & 15;
        int brow0 = wn * 64 + (i16 & 7);
#pragma unroll
        for (int kk = 0; kk < 2; kk++) {
            int acol = kk * 16 + (lane >> 4) * 8;
#pragma unroll
            for (int mi = 0; mi < 2; mi++) {
                uint32_t base = sb + (uint32_t)((arow + mi * 16) * PAD + acol) * 2u;
                aAddr[kk][mi][0] = base;
                aAddr[kk][mi][1] = base + MS;
            }
            int bcol = kk * 16 + ((i16 >> 3) & 1) * 8;
            bAddr[kk] = sb + 2 * MS + (uint32_t)(brow0 * PAD + bcol) * 2u;
        }
    }

    float acc[2][8][4];
#pragma unroll
    for (int mi = 0; mi < 2; mi++)
#pragma unroll
        for (int ni = 0; ni < 8; ni++)
#pragma unroll
            for (int j = 0; j < 4; j++) acc[mi][ni][j] = 0.f;

    auto stage = [&](int buf) {
#pragma unroll
        for (int i = 0; i < 2; i++) {
            uint32_t d = dst0[i] + buf * BSZ;
            CP16(d,          pAh[i], szp[i]);
            CP16(d + MS,     pAl[i], szp[i]);
            CP16(d + 2 * MS, pBh[i], 16);
            CP16(d + 3 * MS, pBl[i], 16);
            pAh[i] += TBK; pAl[i] += TBK; pBh[i] += TBK; pBl[i] += TBK;
        }
    };

    auto compute = [&](uint32_t bo) {
#pragma unroll
        for (int kk = 0; kk < 2; kk++) {
            uint32_t ah[2][4], al[2][4];
#pragma unroll
            for (int mi = 0; mi < 2; mi++) {
                ldsm_x4(ah[mi], aAddr[kk][mi][0] + bo);
                ldsm_x4(al[mi], aAddr[kk][mi][1] + bo);
            }
            uint32_t bb = bAddr[kk] + bo;
#pragma unroll
            for (int ni = 0; ni < 8; ni++) {
                uint32_t bh[2], bl[2];
                ldsm_x2(bh, bb + ni * (8 * PAD * 2));
                ldsm_x2(bl, bb + ni * (8 * PAD * 2) + MS);
#pragma unroll
                for (int mi = 0; mi < 2; mi++) {
                    mma16816(acc[mi][ni], ah[mi], bh);
                    mma16816(acc[mi][ni], ah[mi], bl);
                    mma16816(acc[mi][ni], al[mi], bh);
                }
            }
        }
    };

    int nt = K / TBK;
    stage(0);
    CPCOMMIT();
    for (int t = 0; t < nt; t++) {
        if (t + 1 < nt) {
            stage((t + 1) & 1);
            CPCOMMIT();
            CPWAIT1();
        } else {
            CPWAIT0();
        }
        __syncthreads();
        compute((uint32_t)(t & 1) * BSZ);
        __syncthreads();
    }

    // ---- epilogue
#pragma unroll
    for (int mi = 0; mi < 2; mi++) {
        int rb = row0 + wm * 32 + mi * 16 + (lane >> 2);
        int rows[2] = {rb, rb + 8};
        int tr[2] = {0, 0}; float gate[2] = {0.f, 0.f};
        if (MODE == 2) {
#pragma unroll
            for (int j = 0; j < 2; j++) {
                if (rows[j] < Me) {
                    tr[j] = rowmap[z * S_ + rows[j]];
                    gate[j] = gates[z * S_ + rows[j]];
                }
            }
        }
#pragma unroll
        for (int ni = 0; ni < 8; ni++) {
            int c0 = col0 + wn * 64 + ni * 8 + (lane & 3) * 2;
            if (c0 >= N) continue;
#pragma unroll
            for (int j = 0; j < 2; j++) {
                int gm = rows[j];
                if (gm >= Me) continue;
                float v0 = acc[mi][ni][j * 2 + 0];
                float v1 = acc[mi][ni][j * 2 + 1];
                if (MODE == 0) {
                    size_t ix = (size_t)z * zsC + (size_t)gm * ldc + c0;
                    C[ix] = v0; C[ix + 1] = v1;
                    if (WS) { st_split(Ch, Cl, ix, v0); st_split(Ch, Cl, ix + 1, v1); }
                } else if (MODE == 3) {
                    size_t ix = (size_t)gm * ldc + c0;
                    C[ix]     = v0 + extra[ix];
                    C[ix + 1] = v1 + extra[ix + 1];
                } else if (MODE == 1) {
                    size_t ix = (size_t)(z * S_ + gm) * ldc + c0;
                    st_split(Ch, Cl, ix,     gelu_exact(v0 + bias[c0]));
                    st_split(Ch, Cl, ix + 1, gelu_exact(v1 + bias[c0 + 1]));
                } else { // MODE 2
                    atomicAdd(&C[(size_t)tr[j] * ldc + c0],     gate[j] * (v0 + bias[c0]));
                    atomicAdd(&C[(size_t)tr[j] * ldc + c0 + 1], gate[j] * (v1 + bias[c0 + 1]));
                }
            }
        }
    }
}

// ---------------- rmsnorm (fp32 out) ----------------
__global__ void rms_kernel(const float* __restrict__ x, int istride,
                           const float* __restrict__ w, float* __restrict__ out, int n) {
    int row = blockIdx.x;
    const float* xr = x + (size_t)row * istride;
    __shared__ float red[256];
    float s = 0.f;
    for (int d = threadIdx.x; d < n; d += 256) { float v = xr[d]; s += v * v; }
    red[threadIdx.x] = s;
    __syncthreads();
    for (int o = 128; o > 0; o >>= 1) {
        if (threadIdx.x < o) red[threadIdx.x] += red[threadIdx.x + o];
        __syncthreads();
    }
    float scale = rsqrtf(red[0] / (float)n + 1e-6f);
    for (int d = threadIdx.x; d < n; d += 256)
        out[(size_t)row * n + d] = xr[d] * scale * w[d];
}

// ---------------- rmsnorm (split bf16 out) ----------------
__global__ void rms_split_kernel(const float* __restrict__ x, int istride,
                                 const float* __restrict__ w,
                                 __nv_bfloat16* __restrict__ oh, __nv_bfloat16* __restrict__ ol,
                                 int n) {
    int row = blockIdx.x;
    const float* xr = x + (size_t)row * istride;
    __shared__ float red[256];
    float s = 0.f;
    for (int d = threadIdx.x; d < n; d += 256) { float v = xr[d]; s += v * v; }
    red[threadIdx.x] = s;
    __syncthreads();
    for (int o = 128; o > 0; o >>= 1) {
        if (threadIdx.x < o) red[threadIdx.x] += red[threadIdx.x + o];
        __syncthreads();
    }
    float scale = rsqrtf(red[0] / (float)n + 1e-6f);
    for (int d = threadIdx.x; d < n; d += 256)
        st_split(oh, ol, (size_t)row * n + d, xr[d] * scale * w[d]);
}

// ---------------- RoPE (on fused buffer) ----------------
__global__ void rope_kernel() {
    int s = blockIdx.x;
    int tid = threadIdx.x;
    for (int t = tid; t < H_ * 32; t += blockDim.x) {
        int h = t >> 5, i = t & 31;
        float freq = powf(10000.f, -(float)i / 32.f);
        float ang = (float)s * freq;
        float cs = cosf(ang), sn = sinf(ang);
        float* p = g_f + (size_t)s * FN + h * (DN_ + DR_) + DN_;
        float a = p[i], b = p[i + 32];
        p[i]      = a * cs - b * sn;
        p[i + 32] = b * cs + a * sn;
    }
    if (tid < 32) {
        int i = tid;
        float freq = powf(10000.f, -(float)i / 32.f);
        float ang = (float)s * freq;
        float cs = cosf(ang), sn = sinf(ang);
        const float* p = g_f + (size_t)s * FN + FCKV + R_;
        float a = p[i], b = p[i + 32];
        g_kr[(size_t)s * DR_ + i]      = a * cs - b * sn;
        g_kr[(size_t)s * DR_ + i + 32] = b * cs + a * sn;
    }
}

// ---------------- indexer scores ----------------
__global__ void idx_kernel(float* __restrict__ idx_out) {
    int q = blockIdx.x;
    __shared__ float qs[HI_ * DI_];
    __shared__ float wq[HI_];
    __shared__ float kis[128 * 65];
    int tid = threadIdx.x; // 128
    for (int t = tid; t < HI_ * DI_; t += 128) qs[t] = g_f[(size_t)q * FN + FQI + t];
    if (tid < HI_) wq[tid] = g_f[(size_t)q * FN + FWG + tid];
    for (int kt = 0; kt < S_; kt += 128) {
        __syncthreads();
        for (int t = tid; t < 128 * DI_; t += 128)
            kis[(t >> 6) * 65 + (t & 63)] = g_f[(size_t)(kt + (t >> 6)) * FN + FKI + (t & 63)];
        __syncthreads();
        int k = kt + tid;
        float sc;
        if (k > q) {
            sc = -FLT_MAX;
        } else {
            sc = 0.f;
            const float* krw = &kis[tid * 65];
#pragma unroll
            for (int h = 0; h < HI_; h++) {
                float d = 0.f;
#pragma unroll 8
                for (int dd = 0; dd < DI_; dd++) d += qs[h * DI_ + dd] * krw[dd];
                sc += wq[h] * fmaxf(d, 0.f);
            }
        }
        idx_out[(size_t)q * S_ + k] = sc;
    }
}

// ---------------- exact top-k ----------------
__device__ __forceinline__ unsigned fkey(float f) {
    unsigned u = __float_as_uint(f);
    return (u & 0x80000000u) ? ~u : (u | 0x80000000u);
}

__global__ void topk_kernel(const float* __restrict__ idx_scores) {
    int q = blockIdx.x;
    int n = q + 1;
    int tid = threadIdx.x; // 256
    if (n <= KTOP_) {
        for (int k = tid; k < n; k += blockDim.x) g_sel[(size_t)q * KTOP_ + k] = k;
        if (tid == 0) g_selcnt[q] = n;
        return;
    }
    const float* row = idx_scores + (size_t)q * S_;
    __shared__ unsigned hist[256];
    __shared__ unsigned sh_prefix;
    __shared__ int sh_rem;
    __shared__ int sh_cnt;
    if (tid == 0) { sh_prefix = 0u; sh_rem = KTOP_; sh_cnt = 0; }
    __syncthreads();
    for (int p = 3; p >= 0; p--) {
        for (int b = tid; b < 256; b += blockDim.x) hist[b] = 0u;
        __syncthreads();
        unsigned pre = sh_prefix;
        int shift = 8 * (p + 1);
        for (int k = tid; k < n; k += blockDim.x) {
            unsigned u = fkey(row[k]);
            bool ok = (p == 3) || ((u >> shift) == (pre >> shift));
            if (ok) atomicAdd(&hist[(u >> (8 * p)) & 255u], 1u);
        }
        __syncthreads();
        if (tid == 0) {
            int rem = sh_rem;
            int d;
            for (d = 255; d >= 0; d--) {
                int c = (int)hist[d];
                if (c >= rem) break;
                rem -= c;
            }
            if (d < 0) d = 0;
            sh_prefix = pre | ((unsigned)d << (8 * p));
            sh_rem = rem;
        }
        __syncthreads();
    }
    unsigned T = sh_prefix;
    for (int k = tid; k < n; k += blockDim.x) {
        unsigned u = fkey(row[k]);
        if (u > T) {
            int pos = atomicAdd(&sh_cnt, 1);
            g_sel[(size_t)q * KTOP_ + pos] = k;
        }
    }
    __syncthreads();
    if (tid == 0) {
        int need = sh_rem;
        int base = sh_cnt;
        int taken = 0;
        for (int k = 0; k < n && taken < need; k++) {
            if (fkey(row[k]) == T) { g_sel[(size_t)q * KTOP_ + base + taken] = k; taken++; }
        }
        g_selcnt[q] = base + taken;   // == 512
    }
}

// ---------------- absorbed sparse attention in c-space ----------------
__global__ __launch_bounds__(512) void attn_abs_kernel() {
    int s = blockIdx.x;
    int tid = threadIdx.x;
    int h = tid >> 5, lane = tid & 31;
    __shared__ float sc[H_][KTOP_];
    __shared__ int sel_s[KTOP_];
    int cnt = g_selcnt[s];
    for (int j = tid; j < cnt; j += 512) sel_s[j] = g_sel[(size_t)s * KTOP_ + j];
    __syncthreads();

    float qt[16];
#pragma unroll
    for (int i = 0; i < 16; i++)
        qt[i] = g_qt[(size_t)s * (H_ * R_) + h * R_ + lane + i * 32];
    float qr0 = g_f[(size_t)s * FN + h * (DN_ + DR_) + DN_ + lane];
    float qr1 = g_f[(size_t)s * FN + h * (DN_ + DR_) + DN_ + 32 + lane];

    const float scale = 0.07216878364870323f; // 1/sqrt(192)
    for (int j = 0; j < cnt; j++) {
        int k = sel_s[j];
        const float* cr = g_c + (size_t)k * R_;
        float p = 0.f;
#pragma unroll
        for (int i = 0; i < 16; i++) p += qt[i] * cr[lane + i * 32];
        const float* krr = g_kr + (size_t)k * DR_;
        p += qr0 * krr[lane] + qr1 * krr[lane + 32];
#pragma unroll
        for (int o = 16; o > 0; o >>= 1) p += __shfl_down_sync(0xffffffffu, p, o);
        if (lane == 0) sc[h][j] = p * scale;
    }
    __syncwarp();

    float m = -FLT_MAX;
    for (int j = lane; j < cnt; j += 32) m = fmaxf(m, sc[h][j]);
#pragma unroll
    for (int o = 16; o > 0; o >>= 1) m = fmaxf(m, __shfl_xor_sync(0xffffffffu, m, o));
    float ssum = 0.f;
    for (int j = lane; j < cnt; j += 32) {
        float e = expf(sc[h][j] - m);
        sc[h][j] = e;
        ssum += e;
    }
#pragma unroll
    for (int o = 16; o > 0; o >>= 1) ssum += __shfl_xor_sync(0xffffffffu, ssum, o);
    float inv = 1.f / ssum;
    __syncwarp();

    float cw[16];
#pragma unroll
    for (int i = 0; i < 16; i++) cw[i] = 0.f;
    for (int j = 0; j < cnt; j++) {
        int k = sel_s[j];
        float w = sc[h][j];
        const float* cr = g_c + (size_t)k * R_;
#pragma unroll
        for (int i = 0; i < 16; i++) cw[i] += w * cr[lane + i * 32];
    }
#pragma unroll
    for (int i = 0; i < 16; i++)
        st_split(aCW_h, aCW_l, (size_t)s * (H_ * R_) + h * R_ + lane + i * 32, cw[i] * inv);
}

// ---------------- router / MoE bookkeeping ----------------
__global__ void zero_small_kernel() {
    int t = threadIdx.x;
    if (t < E_) { g_ecnt[t] = 0; g_epsum[t] = 0.f; }
}

__global__ void router_kernel() {
    int t = blockIdx.x * blockDim.x + threadIdx.x;
    if (t >= S_) return;
    float l[E_];
    float m = -FLT_MAX;
#pragma unroll
    for (int e = 0; e < E_; e++) { l[e] = g_rlog[t * E_ + e]; m = fmaxf(m, l[e]); }
    float sum = 0.f;
#pragma unroll
    for (int e = 0; e < E_; e++) { l[e] = expf(l[e] - m); sum += l[e]; }
    float inv = 1.f / sum;
    float p[E_];
#pragma unroll
    for (int e = 0; e < E_; e++) { p[e] = l[e] * inv; atomicAdd(&g_epsum[e], p[e]); }
    int i0 = 0;
#pragma unroll
    for (int e = 1; e < E_; e++) if (p[e] > p[i0]) i0 = e;
    int i1 = -1;
#pragma unroll
    for (int e = 0; e < E_; e++) if (e != i0 && (i1 < 0 || p[e] > p[i1])) i1 = e;
    float g0 = p[i0], g1 = p[i1];
    float dn = g0 + g1;
    g0 /= dn; g1 /= dn;
    int s0 = atomicAdd(&g_ecnt[i0], 1);
    g_elist[i0 * S_ + s0] = t; g_egate[i0 * S_ + s0] = g0;
    int s1 = atomicAdd(&g_ecnt[i1], 1);
    g_elist[i1 * S_ + s1] = t; g_egate[i1 * S_ + s1] = g1;
}

__global__ void copy_kernel(float* __restrict__ dst, const float* __restrict__ src, int n) {
    int i = blockIdx.x * blockDim.x + threadIdx.x;
    if (i < n) dst[i] = src[i];
}

__global__ void aux_kernel(float* out) {
    float a = 0.f;
    for (int e = 0; e < E_; e++)
        a += ((float)g_ecnt[e] / (float)S_) * (g_epsum[e] / (float)S_);
    *out = (float)E_ * a;
}

// ---------------- launch ----------------
static inline dim3 tg_grid(int M, int N, int Z = 1) {
    return dim3((N + 127) / 128, (M + 127) / 128, Z);
}

template<typename T>
static T* sym(const void* s) { void* p; cudaGetSymbolAddress(&p, s); return (T*)p; }

extern "C" void kernel_launch(void* const* d_in, const int* in_sizes, int n_in,
                              void* d_out, int out_size) {
    const float* x        = (const float*)d_in[0];
    const float* norm1_w  = (const float*)d_in[1];
    const float* norm2_w  = (const float*)d_in[2];
    const float* kv_norm_w= (const float*)d_in[3];
    const float* Wq       = (const float*)d_in[4];
    const float* Wkva     = (const float*)d_in[5];
    const float* Wkvb     = (const float*)d_in[6];
    const float* Wo       = (const float*)d_in[7];
    const float* Wiq      = (const float*)d_in[8];
    const float* Wik      = (const float*)d_in[9];
    const float* Wiw      = (const float*)d_in[10];
    const float* Wr       = (const float*)d_in[11];
    const float* W1       = (const float*)d_in[12];
    const float* b1       = (const float*)d_in[13];
    const float* W2       = (const float*)d_in[14];
    const float* b2       = (const float*)d_in[15];

    float* out     = (float*)d_out;
    float* out_x   = out;
    float* out_aux = out + (size_t)S_ * D_;
    float* out_idx = out + (size_t)S_ * D_ + 1;

    static bool attr_done = false;
    if (!attr_done) {
        cudaFuncSetAttribute(tgemm2<0, false>, cudaFuncAttributeMaxDynamicSharedMemorySize, TGSM);
        cudaFuncSetAttribute(tgemm2<0, true>,  cudaFuncAttributeMaxDynamicSharedMemorySize, TGSM);
        cudaFuncSetAttribute(tgemm2<1, true>,  cudaFuncAttributeMaxDynamicSharedMemorySize, TGSM);
        cudaFuncSetAttribute(tgemm2<2, false>, cudaFuncAttributeMaxDynamicSharedMemorySize, TGSM);
        cudaFuncSetAttribute(tgemm2<3, false>, cudaFuncAttributeMaxDynamicSharedMemorySize, TGSM);
        attr_done = true;
    }

    typedef __nv_bfloat16 bf;
    float* F   = sym<float>(g_f);
    float* Cn  = sym<float>(g_c);
    float* QT  = sym<float>(g_qt);
    float* O   = sym<float>(g_o);
    float* X1  = sym<float>(g_x1);
    float* RL  = sym<float>(g_rlog);
    int*   EL  = sym<int>(g_elist);
    float* EG  = sym<float>(g_egate);
    int*   EC  = sym<int>(g_ecnt);
    bf *pWF_h = sym<bf>(bWF_h), *pWF_l = sym<bf>(bWF_l);
    bf *pWr_h = sym<bf>(bWr_h), *pWr_l = sym<bf>(bWr_l);
    bf *pWkt_h = sym<bf>(bWkt_h), *pWkt_l = sym<bf>(bWkt_l);
    bf *pWvv_h = sym<bf>(bWvv_h), *pWvv_l = sym<bf>(bWvv_l);
    bf *pWo_h = sym<bf>(bWo_h), *pWo_l = sym<bf>(bWo_l);
    bf *pW1_h = sym<bf>(bW1_h), *pW1_l = sym<bf>(bW1_l);
    bf *pW2_h = sym<bf>(bW2_h), *pW2_l = sym<bf>(bW2_l);
    bf *pH_h = sym<bf>(aH_h), *pH_l = sym<bf>(aH_l);
    bf *pF_h = sym<bf>(aF_h), *pF_l = sym<bf>(aF_l);
    bf *pO_h = sym<bf>(aO_h), *pO_l = sym<bf>(aO_l);
    bf *pH2_h = sym<bf>(aH2_h), *pH2_l = sym<bf>(aH2_l);
    bf *pCW_h = sym<bf>(aCW_h), *pCW_l = sym<bf>(aCW_l);
    bf *pHID_h = sym<bf>(aHID_h), *pHID_l = sym<bf>(aHID_l);

    dim3 tb(32, 8);
    // ---- weight prep: fused h-projection B (row offsets into bWF) ----
    tsplit_kernel<<<dim3(64, 96, 1), tb>>>(Wq,   3072, 0, 2048, 3072, pWF_h,                        pWF_l,                        0);
    tsplit_kernel<<<dim3(64, 18, 1), tb>>>(Wkva, 576,  0, 2048, 576,  pWF_h + (size_t)FCKV * 2048,  pWF_l + (size_t)FCKV * 2048,  0);
    tsplit_kernel<<<dim3(64, 8, 1),  tb>>>(Wiq,  256,  0, 2048, 256,  pWF_h + (size_t)FQI * 2048,   pWF_l + (size_t)FQI * 2048,   0);
    tsplit_kernel<<<dim3(64, 2, 1),  tb>>>(Wik,  64,   0, 2048, 64,   pWF_h + (size_t)FKI * 2048,   pWF_l + (size_t)FKI * 2048,   0);
    tsplit_kernel<<<dim3(64, 1, 1),  tb>>>(Wiw,  4,    0, 2048, 4,    pWF_h + (size_t)FWG * 2048,   pWF_l + (size_t)FWG * 2048,   0);
    tsplit_kernel<<<dim3(64, 4, 1),  tb>>>(Wr,   4,    0, 2048, 4,    pWr_h, pWr_l, 0);
    tsplit_kernel<<<dim3(64, 64, 1), tb>>>(Wo,   2048, 0, 2048, 2048, pWo_h, pWo_l, 0);
    tsplit_kernel<<<dim3(64, 256, 4), tb>>>(W1,  8192, (size_t)D_ * DFF_, 2048, 8192, pW1_h, pW1_l, (size_t)DFF_ * D_);
    tsplit_kernel<<<dim3(256, 64, 4), tb>>>(W2,  2048, (size_t)DFF_ * D_, 8192, 2048, pW2_h, pW2_l, (size_t)D_ * DFF_);
    tsplit_kernel<<<dim3(16, 4, 16),  tb>>>(Wkvb + DN_, H_ * (DN_ + DV_), 256, 512, 128, pWvv_h, pWvv_l, (size_t)DV_ * R_);
    wktsplit_kernel<<<(H_ * R_ * DN_ + 255) / 256, 256>>>(Wkvb, pWkt_h, pWkt_l);

    // 1. h = rms(x) -> split
    rms_split_kernel<<<S_, 256>>>(x, D_, norm1_w, pH_h, pH_l, D_);
    // 2. FUSED projections: [q | ckv | qi | ki | wgt] = h @ [Wq|Wkva|Wiq|Wik|Wiw]
    tgemm2<0, true><<<tg_grid(S_, FNR), 256, TGSM>>>(pH_h, pH_l, D_, 0, pWF_h, pWF_l, 0,
        F, FN, 0, pF_h, pF_l, S_, FNR, D_, nullptr, nullptr, nullptr, nullptr);
    // 3. c = rms(ckv[:, :R])
    rms_kernel<<<S_, 256>>>(F + FCKV, FN, kv_norm_w, Cn, R_);
    // 4. RoPE (in fused buffer)
    rope_kernel<<<S_, 256>>>();
    // 5. q̃ = q_nope @ WkvbT (per-head)
    tgemm2<0, false><<<tg_grid(S_, R_, H_), 256, TGSM>>>(pF_h, pF_l, FN, (size_t)(DN_ + DR_),
        pWkt_h, pWkt_l, (size_t)R_ * DN_,
        QT, H_ * R_, (size_t)R_, nullptr, nullptr, S_, R_, DN_, nullptr, nullptr, nullptr, nullptr);
    // 6. indexer + top-k
    idx_kernel<<<S_, 128>>>(out_idx);
    topk_kernel<<<S_, 256>>>(out_idx);
    // 7. absorbed sparse attention -> cw split
    attn_abs_kernel<<<S_, 512>>>();
    // 8. o = cw @ Wkvb_v (per-head, fp32 + split)
    tgemm2<0, true><<<tg_grid(S_, DV_, H_), 256, TGSM>>>(pCW_h, pCW_l, H_ * R_, (size_t)R_,
        pWvv_h, pWvv_l, (size_t)DV_ * R_,
        O, H_ * DV_, (size_t)DV_, pO_h, pO_l, S_, DV_, R_, nullptr, nullptr, nullptr, nullptr);
    // 9. x1 = o@Wo + x
    tgemm2<3, false><<<tg_grid(S_, D_), 256, TGSM>>>(pO_h, pO_l, H_ * DV_, 0, pWo_h, pWo_l, 0,
        X1, D_, 0, nullptr, nullptr, S_, D_, H_ * DV_, x, nullptr, nullptr, nullptr);
    // 10. h2 = rms(x1) -> split
    rms_split_kernel<<<S_, 256>>>(X1, D_, norm2_w, pH2_h, pH2_l, D_);
    // 11. router logits
    tgemm2<0, false><<<tg_grid(S_, E_), 256, TGSM>>>(pH2_h, pH2_l, D_, 0, pWr_h, pWr_l, 0,
        RL, E_, 0, nullptr, nullptr, S_, E_, D_, nullptr, nullptr, nullptr, nullptr);
    // 12. router
    zero_small_kernel<<<1, 32>>>();
    router_kernel<<<S_ / 256, 256>>>();
    // 13. out_x = x1
    copy_kernel<<<(S_ * D_ + 255) / 256, 256>>>(out_x, X1, S_ * D_);
    // 14. MoE up: hid(split) = gelu(h2[tok]@W1[e] + b1[e])
    tgemm2<1, true><<<tg_grid(S_, DFF_, E_), 256, TGSM>>>(pH2_h, pH2_l, D_, 0,
        pW1_h, pW1_l, (size_t)DFF_ * D_,
        nullptr, DFF_, 0, pHID_h, pHID_l, S_, DFF_, D_, b1, EL, nullptr, EC);
    // 15. MoE down: out_x[tok] += gate*(hid@W2[e] + b2[e])
    tgemm2<2, false><<<tg_grid(S_, D_, E_), 256, TGSM>>>(pHID_h, pHID_l, DFF_, 0,
        pW2_h, pW2_l, (size_t)D_ * DFF_,
        out_x, D_, 0, nullptr, nullptr, S_, D_, DFF_, b2, EL, EG, EC);
    // 16. aux
    aux_kernel<<<1, 1>>>(out_aux);
}